// round 14
// baseline (speedup 1.0000x reference)
#include <cuda_runtime.h>
#include <cuda_bf16.h>
#include <cstdint>

// ---------------- HMMA / misc helpers (family-portable: sm_80+) ----------------
__device__ __forceinline__ uint32_t smem_u32(const void* p) {
    uint32_t a;
    asm("{ .reg .u64 t; cvta.to.shared.u64 t, %1; cvt.u32.u64 %0, t; }" : "=r"(a) : "l"(p));
    return a;
}
__device__ __forceinline__ void ldsm4(uint32_t r[4], uint32_t addr) {
    asm volatile("ldmatrix.sync.aligned.m8n8.x4.shared.b16 {%0,%1,%2,%3}, [%4];"
        : "=r"(r[0]), "=r"(r[1]), "=r"(r[2]), "=r"(r[3]) : "r"(addr));
}
__device__ __forceinline__ void mma_k16(float c[4], const uint32_t a[4], uint32_t b0, uint32_t b1) {
    asm volatile("mma.sync.aligned.m16n8k16.row.col.f32.bf16.bf16.f32 "
        "{%0,%1,%2,%3}, {%4,%5,%6,%7}, {%8,%9}, {%0,%1,%2,%3};"
        : "+f"(c[0]), "+f"(c[1]), "+f"(c[2]), "+f"(c[3])
        : "r"(a[0]), "r"(a[1]), "r"(a[2]), "r"(a[3]), "r"(b0), "r"(b1));
}
__device__ __forceinline__ void mma_k8(float c[4], uint32_t a0, uint32_t a1, uint32_t b0) {
    asm volatile("mma.sync.aligned.m16n8k8.row.col.f32.bf16.bf16.f32 "
        "{%0,%1,%2,%3}, {%4,%5}, {%6}, {%0,%1,%2,%3};"
        : "+f"(c[0]), "+f"(c[1]), "+f"(c[2]), "+f"(c[3])
        : "r"(a0), "r"(a1), "r"(b0));
}
__device__ __forceinline__ uint32_t pbf2(float lo, float hi) {   // low half = lo
    uint32_t r; asm("cvt.rn.bf16x2.f32 %0, %1, %2;" : "=r"(r) : "f"(hi), "f"(lo)); return r;
}
__device__ __forceinline__ unsigned short bf16rn(float f) {
    unsigned short u; asm("cvt.rn.bf16.f32 %0, %1;" : "=h"(u) : "f"(f)); return u;
}
__device__ __forceinline__ float sin_ap(float x) {
    float r; asm("sin.approx.f32 %0, %1;" : "=f"(r) : "f"(x)); return r;
}
__device__ __forceinline__ float ex2_ap(float x) {
    float r; asm("ex2.approx.f32 %0, %1;" : "=f"(r) : "f"(x)); return r;
}
__device__ __forceinline__ void split2(float a, float b, uint32_t& h, uint32_t& l) {
    uint32_t ba = __float_as_uint(a), bb = __float_as_uint(b);
    h = __byte_perm(ba, bb, 0x7632);
    l = pbf2(a - __uint_as_float(ba & 0xFFFF0000u),
             b - __uint_as_float(bb & 0xFFFF0000u));
}

// ---------------- problem constants ----------------
#define Bn   16
#define Nn   2048
#define DIN  512
#define DK   10
#define NH   2
#define DH   5
#define HID  20
#define DOUT 512
#define ROWS (Bn * Nn)             // 32768
#define KZ   2

// ---------------- device scratch ----------------
__device__ uint32_t g_Qb[32][Nn][8];       // split-bf16: [0..3]=hi pairs, [4..7]=lo
__device__ uint32_t g_Kb[32][Nn][8];
__device__ unsigned short g_Vth[32][5][Nn];  // V transposed, hi plane
__device__ unsigned short g_Vtl[32][5][Nn];  // lo plane
__device__ float g_A[32][Nn][KZ][8];         // partials: a0..a4, den
__device__ float g_P[2][ROWS][32];           // proj fp32 partials per K-half

// =====================================================================
// Kernel 1a: QKV projection on HMMA, SPLIT ALONG K (blockIdx.y = K-half).
// 128 rows/block, 4 chunks of 64 k; raw fp32 partials to g_P.
// Grid (256, 2) -> 512 blocks => 2 resident blocks/SM (reg-limited).
// =====================================================================
#define XSTR 72
#define XH_OFF 0
#define XL_OFF (128 * XSTR * 2)
#define WH_OFF (2 * 128 * XSTR * 2)
#define WL_OFF (WH_OFF + 32 * XSTR * 2)
#define SM_TOT (WL_OFF + 32 * XSTR * 2)

__global__ __launch_bounds__(256) void proj_tc(
    const float* __restrict__ x,
    const float* __restrict__ Wq,
    const float* __restrict__ Wk,
    const float* __restrict__ Wv)
{
    __shared__ __align__(16) char sm[SM_TOT];
    const uint32_t sb = smem_u32(sm);

    const int tid  = threadIdx.x;
    const int wid  = tid >> 5;
    const int lane = tid & 31;
    const int row0 = blockIdx.x * 128;
    const int kh   = blockIdx.y;             // K-half: 0 or 1
    const int kbase0 = kh * 256;
    const int m0   = wid * 16;

    float C[4][4];
#pragma unroll
    for (int t = 0; t < 4; t++)
#pragma unroll
        for (int i = 0; i < 4; i++) C[t][i] = 0.f;

    float4 xr[8];
    float  wr[8];
#pragma unroll
    for (int it = 0; it < 8; it++) {
        int e = tid + it * 256;
        int r = e >> 4, c4 = e & 15;
        xr[it] = *reinterpret_cast<const float4*>(
            x + (size_t)(row0 + r) * DIN + kbase0 + c4 * 4);
    }
#pragma unroll
    for (int it = 0; it < 8; it++) {
        int e = tid + it * 256;
        int k = kbase0 + (e >> 5), j = e & 31;
        wr[it] = (j < 10) ? Wq[k * DK + j]
               : (j < 20) ? Wk[k * DK + (j - 10)]
               : (j < 30) ? Wv[k * DK + (j - 20)] : 0.f;
    }

    const int arow = lane & 15;
    const int agrp = lane >> 4;
    const int bn = lane >> 2;
    const int bk0 = (lane & 3) * 2;

    for (int c = 0; c < 4; c++) {
        __syncthreads();
#pragma unroll
        for (int it = 0; it < 8; it++) {
            int e = tid + it * 256;
            int r = e >> 4, c4 = e & 15;
            float4 v = xr[it];
            uint32_t h01, l01, h23, l23;
            split2(v.x, v.y, h01, l01);
            split2(v.z, v.w, h23, l23);
            uint32_t off = (r * XSTR + c4 * 4) * 2;
            *reinterpret_cast<uint2*>(sm + XH_OFF + off) = make_uint2(h01, h23);
            *reinterpret_cast<uint2*>(sm + XL_OFF + off) = make_uint2(l01, l23);
        }
#pragma unroll
        for (int it = 0; it < 8; it++) {
            int e = tid + it * 256;
            int k = e >> 5, j = e & 31;
            float w = wr[it];
            uint32_t wb = __float_as_uint(w);
            uint32_t off = (j * XSTR + k) * 2;
            *reinterpret_cast<unsigned short*>(sm + WH_OFF + off) = (unsigned short)(wb >> 16);
            *reinterpret_cast<unsigned short*>(sm + WL_OFF + off) =
                bf16rn(w - __uint_as_float(wb & 0xFFFF0000u));
        }
        __syncthreads();

        if (c < 3) {
            const int kc = kbase0 + (c + 1) * 64;
#pragma unroll
            for (int it = 0; it < 8; it++) {
                int e = tid + it * 256;
                int r = e >> 4, c4 = e & 15;
                xr[it] = *reinterpret_cast<const float4*>(
                    x + (size_t)(row0 + r) * DIN + kc + c4 * 4);
            }
#pragma unroll
            for (int it = 0; it < 8; it++) {
                int e = tid + it * 256;
                int k = kc + (e >> 5), j = e & 31;
                wr[it] = (j < 10) ? Wq[k * DK + j]
                       : (j < 20) ? Wk[k * DK + (j - 10)]
                       : (j < 30) ? Wv[k * DK + (j - 20)] : 0.f;
            }
        }

#pragma unroll
        for (int ks = 0; ks < 4; ks++) {
            uint32_t ah[4], al[4];
            uint32_t abase = (m0 + arow) * (XSTR * 2) + ks * 32 + agrp * 16;
            ldsm4(ah, sb + XH_OFF + abase);
            ldsm4(al, sb + XL_OFF + abase);
#pragma unroll
            for (int t = 0; t < 4; t++) {
                uint32_t boff = ((bn + t * 8) * XSTR + ks * 16 + bk0) * 2;
                uint32_t bh0 = *reinterpret_cast<const uint32_t*>(sm + WH_OFF + boff);
                uint32_t bh1 = *reinterpret_cast<const uint32_t*>(sm + WH_OFF + boff + 16);
                uint32_t bl0 = *reinterpret_cast<const uint32_t*>(sm + WL_OFF + boff);
                uint32_t bl1 = *reinterpret_cast<const uint32_t*>(sm + WL_OFF + boff + 16);
                mma_k16(C[t], ah, bh0, bh1);
                mma_k16(C[t], ah, bl0, bl1);
                mma_k16(C[t], al, bh0, bh1);
            }
        }
    }

    // ---- C frags -> smem transpose (stride 33), then fp32 partial STG ----
    __syncthreads();
    float* co = reinterpret_cast<float*>(sm);
    {
        const int r_c = lane >> 2;
        const int j2  = (lane & 3) * 2;
#pragma unroll
        for (int t = 0; t < 4; t++) {
            float* p0 = co + (m0 + r_c) * 33 + t * 8 + j2;
            float* p1 = co + (m0 + r_c + 8) * 33 + t * 8 + j2;
            p0[0] = C[t][0]; p0[1] = C[t][1];
            p1[0] = C[t][2]; p1[1] = C[t][3];
        }
    }
    __syncthreads();

    if (tid < 128) {
        const float* src = co + tid * 33;
        float* gp = &g_P[kh][row0 + tid][0];
#pragma unroll
        for (int i = 0; i < 7; i++) {
            float4 v = make_float4(src[4*i], src[4*i+1], src[4*i+2], src[4*i+3]);
            reinterpret_cast<float4*>(gp)[i] = v;
        }
        reinterpret_cast<float4*>(gp)[7] = make_float4(src[28], src[29], 0.f, 0.f);
    }
}

// =====================================================================
// Kernel 1b: combine K-half partials + bias + split-bf16 emit.
// 1 row per thread; grid 128 x 256.
// =====================================================================
__global__ __launch_bounds__(256) void proj_fin(
    const float* __restrict__ bq, const float* __restrict__ bk,
    const float* __restrict__ bv)
{
    const int grow = blockIdx.x * 256 + threadIdx.x;
    float o[32];
    const float4* p0 = reinterpret_cast<const float4*>(&g_P[0][grow][0]);
    const float4* p1 = reinterpret_cast<const float4*>(&g_P[1][grow][0]);
#pragma unroll
    for (int i = 0; i < 8; i++) {
        float4 a = p0[i], b = p1[i];
        o[4*i+0] = a.x + b.x; o[4*i+1] = a.y + b.y;
        o[4*i+2] = a.z + b.z; o[4*i+3] = a.w + b.w;
    }

    const int b = grow >> 11, n = grow & (Nn - 1);
    const float rs = 0.4472135954999579f;   // 1/sqrt(5)

    float q[10], kk[10], vv[10];
#pragma unroll
    for (int j = 0; j < 10; j++) {
        q[j]  = (o[j]      + bq[j]) * rs;
        kk[j] = (o[j + 10] + bk[j]);
        vv[j] = (o[j + 20] + bv[j]);
    }
#pragma unroll
    for (int h = 0; h < 2; h++) {
        int bh = b * NH + h;
        uint32_t qh[4], ql[4], kh[4], kl[4];
        split2(q[h*5+0], q[h*5+1], qh[0], ql[0]);
        split2(q[h*5+2], q[h*5+3], qh[1], ql[1]);
        split2(q[h*5+4], 0.f,      qh[2], ql[2]);
        qh[3] = 0; ql[3] = 0;
        split2(kk[h*5+0], kk[h*5+1], kh[0], kl[0]);
        split2(kk[h*5+2], kk[h*5+3], kh[1], kl[1]);
        split2(kk[h*5+4], 0.f,       kh[2], kl[2]);
        kh[3] = 0; kl[3] = 0;
        *reinterpret_cast<uint4*>(&g_Qb[bh][n][0]) = make_uint4(qh[0], qh[1], qh[2], qh[3]);
        *reinterpret_cast<uint4*>(&g_Qb[bh][n][4]) = make_uint4(ql[0], ql[1], ql[2], ql[3]);
        *reinterpret_cast<uint4*>(&g_Kb[bh][n][0]) = make_uint4(kh[0], kh[1], kh[2], kh[3]);
        *reinterpret_cast<uint4*>(&g_Kb[bh][n][4]) = make_uint4(kl[0], kl[1], kl[2], kl[3]);
#pragma unroll
        for (int d = 0; d < 5; d++) {
            float v = vv[h*5+d];
            uint32_t vb = __float_as_uint(v);
            g_Vth[bh][d][n] = (unsigned short)(vb >> 16);
            g_Vtl[bh][d][n] = bf16rn(v - __uint_as_float(vb & 0xFFFF0000u));
        }
    }
}

// =====================================================================
// Kernel 2: HMMA attention (R12 best config, KZ=2).
// Block = 8 warps x 16 q = 128 queries; 128-key chunks; register-
// prefetched chunk staging; ones-column PV trick; in-fragment mask.
// =====================================================================
#define AQH 0
#define AQL 2048
#define AKH 4096
#define AKL 6144
#define AVH 8192
#define AVL (AVH + 8 * 136 * 2)       // 10368
#define AT_SM (AVL + 8 * 136 * 2)     // 12544

__global__ __launch_bounds__(256) void attn_tc()
{
    __shared__ __align__(16) char sm[AT_SM];

    const int tid  = threadIdx.x;
    const int wid  = tid >> 5;
    const int lane = tid & 31;
    const int qt   = (Nn / 128 - 1) - blockIdx.x;    // heavy tiles first
    const int bh   = blockIdx.y;
    const int kz   = blockIdx.z;
    const int m0   = wid * 16;
    const int r    = lane >> 2;
    const int j    = lane & 3;

    const int nt = qt + 1;
    const int t0 = (nt * kz) / KZ, t1 = (nt * (kz + 1)) / KZ;

    float Cpv[4] = {0.f, 0.f, 0.f, 0.f};
    const float LOG2E = 1.4426950408889634f;

    if (t0 < t1) {
        for (int e = tid; e < 3 * 136; e += 256) {
            int d = 5 + e / 136, kk2 = e % 136;
            *reinterpret_cast<unsigned short*>(sm + AVH + (d * 136 + kk2) * 2) =
                (d == 5) ? (unsigned short)0x3F80 : (unsigned short)0;
            *reinterpret_cast<unsigned short*>(sm + AVL + (d * 136 + kk2) * 2) = 0;
        }
        if (tid < 128) {
            uint4 h = *reinterpret_cast<const uint4*>(&g_Qb[bh][qt * 128 + tid][0]);
            uint4 l = *reinterpret_cast<const uint4*>(&g_Qb[bh][qt * 128 + tid][4]);
            *reinterpret_cast<uint4*>(sm + AQH + tid * 16) = h;
            *reinterpret_cast<uint4*>(sm + AQL + tid * 16) = l;
        }
        __syncthreads();

        uint32_t qh0, qh1, ql0, ql1;
        {
            uint32_t w0 = (m0 + r) * 16 + j * 4;
            uint32_t w1 = (m0 + r + 8) * 16 + j * 4;
            qh0 = *reinterpret_cast<const uint32_t*>(sm + AQH + w0);
            qh1 = *reinterpret_cast<const uint32_t*>(sm + AQH + w1);
            ql0 = *reinterpret_cast<const uint32_t*>(sm + AQL + w0);
            ql1 = *reinterpret_cast<const uint32_t*>(sm + AQL + w1);
        }

        uint32_t vr[5];
        uint4 kh4, kl4;
        const int key = tid & 127;

        {
            const int key0 = t0 * 128;
            if (tid < 128) {
#pragma unroll
                for (int it = 0; it < 5; it++) {
                    int e = tid + it * 128;
                    int pl = e / 320, rem = e % 320;
                    int d = rem >> 6, kp = rem & 63;
                    vr[it] = pl
                        ? *reinterpret_cast<const uint32_t*>(&g_Vtl[bh][d][key0 + 2 * kp])
                        : *reinterpret_cast<const uint32_t*>(&g_Vth[bh][d][key0 + 2 * kp]);
                }
            } else {
                kh4 = *reinterpret_cast<const uint4*>(&g_Kb[bh][key0 + key][0]);
                kl4 = *reinterpret_cast<const uint4*>(&g_Kb[bh][key0 + key][4]);
            }
        }

        for (int ck = t0; ck < t1; ck++) {
            __syncthreads();
            if (tid < 128) {
#pragma unroll
                for (int it = 0; it < 5; it++) {
                    int e = tid + it * 128;
                    int pl = e / 320, rem = e % 320;
                    int d = rem >> 6, kp = rem & 63;
                    *reinterpret_cast<uint32_t*>(
                        sm + (pl ? AVL : AVH) + (d * 136 + 2 * kp) * 2) = vr[it];
                }
            } else {
                *reinterpret_cast<uint4*>(sm + AKH + key * 16) = kh4;
                *reinterpret_cast<uint4*>(sm + AKL + key * 16) = kl4;
            }
            __syncthreads();

            if (ck + 1 < t1) {
                const int key0 = (ck + 1) * 128;
                if (tid < 128) {
#pragma unroll
                    for (int it = 0; it < 5; it++) {
                        int e = tid + it * 128;
                        int pl = e / 320, rem = e % 320;
                        int d = rem >> 6, kp = rem & 63;
                        vr[it] = pl
                            ? *reinterpret_cast<const uint32_t*>(&g_Vtl[bh][d][key0 + 2 * kp])
                            : *reinterpret_cast<const uint32_t*>(&g_Vth[bh][d][key0 + 2 * kp]);
                    }
                } else {
                    kh4 = *reinterpret_cast<const uint4*>(&g_Kb[bh][key0 + key][0]);
                    kl4 = *reinterpret_cast<const uint4*>(&g_Kb[bh][key0 + key][4]);
                }
            }

            const bool diag = (ck == qt);

#pragma unroll 2
            for (int ks = 0; ks < 8; ks++) {
                const int kbase = ks * 16;
                if (diag && kbase > m0 + 15) break;
                const bool needMask = diag && (kbase + 15 > m0);

                float c0[4] = {0.f,0.f,0.f,0.f}, c1[4] = {0.f,0.f,0.f,0.f};
                {
                    uint32_t o0 = (kbase + r) * 16 + j * 4;
                    uint32_t o1 = (kbase + 8 + r) * 16 + j * 4;
                    uint32_t b0h = *reinterpret_cast<const uint32_t*>(sm + AKH + o0);
                    uint32_t b0l = *reinterpret_cast<const uint32_t*>(sm + AKL + o0);
                    uint32_t b1h = *reinterpret_cast<const uint32_t*>(sm + AKH + o1);
                    uint32_t b1l = *reinterpret_cast<const uint32_t*>(sm + AKL + o1);
                    mma_k8(c0, qh0, qh1, b0h);
                    mma_k8(c0, qh0, qh1, b0l);
                    mma_k8(c0, ql0, ql1, b0h);
                    mma_k8(c1, qh0, qh1, b1h);
                    mma_k8(c1, qh0, qh1, b1l);
                    mma_k8(c1, ql0, ql1, b1h);
                }

                float p[8];
#pragma unroll
                for (int i = 0; i < 4; i++) p[i]     = ex2_ap(sin_ap(c0[i]) * LOG2E);
#pragma unroll
                for (int i = 0; i < 4; i++) p[4 + i] = ex2_ap(sin_ap(c1[i]) * LOG2E);

                if (needMask) {
                    int q_lo = m0 + r, q_hi = q_lo + 8;
                    int k00 = kbase + 2 * j, k01 = k00 + 1;
                    int k10 = k00 + 8,       k11 = k01 + 8;
                    p[0] = (k00 <= q_lo) ? p[0] : 0.f;
                    p[1] = (k01 <= q_lo) ? p[1] : 0.f;
                    p[2] = (k00 <= q_hi) ? p[2] : 0.f;
                    p[3] = (k01 <= q_hi) ? p[3] : 0.f;
                    p[4] = (k10 <= q_lo) ? p[4] : 0.f;
                    p[5] = (k11 <= q_lo) ? p[5] : 0.f;
                    p[6] = (k10 <= q_hi) ? p[6] : 0.f;
                    p[7] = (k11 <= q_hi) ? p[7] : 0.f;
                }

                uint32_t ah[4], al[4];
#pragma unroll
                for (int i = 0; i < 4; i++) {
                    uint32_t h = pbf2(p[2*i], p[2*i+1]);
                    ah[i] = h;
                    float r0 = __uint_as_float(h << 16);
                    float r1 = __uint_as_float(h & 0xFFFF0000u);
                    al[i] = pbf2(p[2*i] - r0, p[2*i+1] - r1);
                }

                uint32_t vo = (r * 136 + kbase + 2 * j) * 2;
                uint32_t bvh0 = *reinterpret_cast<const uint32_t*>(sm + AVH + vo);
                uint32_t bvh1 = *reinterpret_cast<const uint32_t*>(sm + AVH + vo + 16);
                uint32_t bvl0 = *reinterpret_cast<const uint32_t*>(sm + AVL + vo);
                uint32_t bvl1 = *reinterpret_cast<const uint32_t*>(sm + AVL + vo + 16);

                mma_k16(Cpv, ah, bvh0, bvh1);
                mma_k16(Cpv, ah, bvl0, bvl1);
                mma_k16(Cpv, al, bvh0, bvh1);
            }
        }
    }

    if (j < 3) {
        int q1 = qt * 128 + m0 + r;
        *reinterpret_cast<float2*>(&g_A[bh][q1][kz][2 * j]) = make_float2(Cpv[0], Cpv[1]);
        int q2 = q1 + 8;
        *reinterpret_cast<float2*>(&g_A[bh][q2][kz][2 * j]) = make_float2(Cpv[2], Cpv[3]);
    }
}

// =====================================================================
// Kernel 3: combine partials + MLP head on HMMA (R11 core, KZ=2).
// =====================================================================
#define MA_H 0
#define MA_L (128 * 40 * 2)
#define MB_H (2 * 128 * 40 * 2)
#define MB_L (MB_H + 128 * 36 * 2)
#define MCS  (MB_L + 128 * 36 * 2)
#define MBM2 (MCS + 128 * 10 * 4)
#define MLP_SM (MBM2 + 512 * 4)

__global__ __launch_bounds__(256) void mlp_tc(
    const float* __restrict__ Wm1, const float* __restrict__ bm1,
    const float* __restrict__ Wm2, const float* __restrict__ bm2,
    float* __restrict__ out)
{
    __shared__ __align__(16) char sm[MLP_SM];
    const uint32_t sb = smem_u32(sm);

    const int tid  = threadIdx.x;
    const int wid  = tid >> 5;
    const int lane = tid & 31;
    const int row0 = blockIdx.x * 128;
    const int m0   = wid * 16;

    float* cs   = reinterpret_cast<float*>(sm + MCS);
    float* bm2s = reinterpret_cast<float*>(sm + MBM2);

    for (int e = tid; e < 128 * 10; e += 256) {
        int r = e / 10, k = e % 10;
        int h = k / DH, d = k % DH;
        int grow = row0 + r;
        int b = grow >> 11, n = grow & (Nn - 1);
        const float* A = g_A[b * NH + h][n][0];
        float den = 0.f, num = 0.f;
#pragma unroll
        for (int s = 0; s < KZ; s++) {
            num += A[8 * s + d];
            den += A[8 * s + 5];
        }
        cs[e] = num * __fdividef(1.f, den);
    }
    for (int e = tid; e < 512; e += 256) bm2s[e] = bm2[e];
    __syncthreads();

    for (int e = tid; e < 128 * 12; e += 256) {
        int r = e / 12, k = 20 + e % 12;
        *reinterpret_cast<unsigned short*>(sm + MA_H + (r * 40 + k) * 2) = 0;
        *reinterpret_cast<unsigned short*>(sm + MA_L + (r * 40 + k) * 2) = 0;
    }
    for (int e = tid; e < 128 * HID; e += 256) {
        int r = e / HID, jj = e % HID;
        const float* crow = cs + r * 10;
        float s = bm1[jj];
#pragma unroll
        for (int k = 0; k < DK; k++)
            s = fmaf(crow[k], Wm1[k * HID + jj], s);
        s = (s > 0.f) ? s : 0.01f * s;
        uint32_t bits = __float_as_uint(s);
        *reinterpret_cast<unsigned short*>(sm + MA_H + (r * 40 + jj) * 2) =
            (unsigned short)(bits >> 16);
        *reinterpret_cast<unsigned short*>(sm + MA_L + (r * 40 + jj) * 2) =
            bf16rn(s - __uint_as_float(bits & 0xFFFF0000u));
    }
    __syncthreads();

    const int arow = lane & 15;
    const int agrp = lane >> 4;
    uint32_t ah[2][4], al[2][4];
#pragma unroll
    for (int ks = 0; ks < 2; ks++) {
        uint32_t abase = (m0 + arow) * 80 + ks * 32 + agrp * 16;
        ldsm4(ah[ks], sb + MA_H + abase);
        ldsm4(al[ks], sb + MA_L + abase);
    }

    const int bn = lane >> 2;
    const int bj = (lane & 3) * 2;
    const int rC = lane >> 2;
    const int jC = lane & 3;

    for (int nc = 0; nc < 4; nc++) {
        __syncthreads();
        for (int e = tid; e < 128 * 32; e += 256) {
            int k = e >> 7, nl = e & 127;
            float w = (k < HID) ? Wm2[k * DOUT + nc * 128 + nl] : 0.f;
            uint32_t wb = __float_as_uint(w);
            *reinterpret_cast<unsigned short*>(sm + MB_H + (nl * 36 + k) * 2) =
                (unsigned short)(wb >> 16);
            *reinterpret_cast<unsigned short*>(sm + MB_L + (nl * 36 + k) * 2) =
                bf16rn(w - __uint_as_float(wb & 0xFFFF0000u));
        }
        __syncthreads();

#pragma unroll 4
        for (int t = 0; t < 16; t++) {
            float C[4] = {0.f, 0.f, 0.f, 0.f};
#pragma unroll
            for (int ks = 0; ks < 2; ks++) {
                uint32_t bo = ((bn + t * 8) * 36 + ks * 16 + bj) * 2;
                uint32_t bh0 = *reinterpret_cast<const uint32_t*>(sm + MB_H + bo);
                uint32_t bh1 = *reinterpret_cast<const uint32_t*>(sm + MB_H + bo + 16);
                uint32_t bl0 = *reinterpret_cast<const uint32_t*>(sm + MB_L + bo);
                uint32_t bl1 = *reinterpret_cast<const uint32_t*>(sm + MB_L + bo + 16);
                mma_k16(C, ah[ks], bh0, bh1);
                mma_k16(C, ah[ks], bl0, bl1);
                mma_k16(C, al[ks], bh0, bh1);
            }
            int n0 = nc * 128 + t * 8;
            float b0 = bm2s[n0 + 2 * jC], b1 = bm2s[n0 + 2 * jC + 1];
            size_t ro = (size_t)(row0 + m0 + rC) * DOUT + n0 + 2 * jC;
            *reinterpret_cast<float2*>(out + ro) = make_float2(C[0] + b0, C[1] + b1);
            *reinterpret_cast<float2*>(out + ro + 8 * DOUT) = make_float2(C[2] + b0, C[3] + b1);
        }
    }
}

// =====================================================================
extern "C" void kernel_launch(void* const* d_in, const int* in_sizes, int n_in,
                              void* d_out, int out_size)
{
    const float* x   = (const float*)d_in[0];
    const float* Wq  = (const float*)d_in[1];
    const float* bq  = (const float*)d_in[2];
    const float* Wk  = (const float*)d_in[3];
    const float* bk  = (const float*)d_in[4];
    const float* Wv  = (const float*)d_in[5];
    const float* bv  = (const float*)d_in[6];
    const float* Wm1 = (const float*)d_in[7];
    const float* bm1 = (const float*)d_in[8];
    const float* Wm2 = (const float*)d_in[9];
    const float* bm2 = (const float*)d_in[10];

    proj_tc<<<dim3(ROWS / 128, 2), 256>>>(x, Wq, Wk, Wv);
    proj_fin<<<ROWS / 256, 256>>>(bq, bk, bv);
    attn_tc<<<dim3(Nn / 128, 32, KZ), 256>>>();
    mlp_tc<<<ROWS / 128, 256>>>(Wm1, bm1, Wm2, bm2, (float*)d_out);
}

// round 15
// speedup vs baseline: 1.0701x; 1.0701x over previous
#include <cuda_runtime.h>
#include <cuda_bf16.h>
#include <cstdint>

// ---------------- HMMA / misc helpers (family-portable: sm_80+) ----------------
__device__ __forceinline__ uint32_t smem_u32(const void* p) {
    uint32_t a;
    asm("{ .reg .u64 t; cvta.to.shared.u64 t, %1; cvt.u32.u64 %0, t; }" : "=r"(a) : "l"(p));
    return a;
}
__device__ __forceinline__ void ldsm4(uint32_t r[4], uint32_t addr) {
    asm volatile("ldmatrix.sync.aligned.m8n8.x4.shared.b16 {%0,%1,%2,%3}, [%4];"
        : "=r"(r[0]), "=r"(r[1]), "=r"(r[2]), "=r"(r[3]) : "r"(addr));
}
__device__ __forceinline__ void mma_k16(float c[4], const uint32_t a[4], uint32_t b0, uint32_t b1) {
    asm volatile("mma.sync.aligned.m16n8k16.row.col.f32.bf16.bf16.f32 "
        "{%0,%1,%2,%3}, {%4,%5,%6,%7}, {%8,%9}, {%0,%1,%2,%3};"
        : "+f"(c[0]), "+f"(c[1]), "+f"(c[2]), "+f"(c[3])
        : "r"(a[0]), "r"(a[1]), "r"(a[2]), "r"(a[3]), "r"(b0), "r"(b1));
}
__device__ __forceinline__ void mma_k8(float c[4], uint32_t a0, uint32_t a1, uint32_t b0) {
    asm volatile("mma.sync.aligned.m16n8k8.row.col.f32.bf16.bf16.f32 "
        "{%0,%1,%2,%3}, {%4,%5}, {%6}, {%0,%1,%2,%3};"
        : "+f"(c[0]), "+f"(c[1]), "+f"(c[2]), "+f"(c[3])
        : "r"(a0), "r"(a1), "r"(b0));
}
__device__ __forceinline__ uint32_t pbf2(float lo, float hi) {   // low half = lo
    uint32_t r; asm("cvt.rn.bf16x2.f32 %0, %1, %2;" : "=r"(r) : "f"(hi), "f"(lo)); return r;
}
__device__ __forceinline__ unsigned short bf16rn(float f) {
    unsigned short u; asm("cvt.rn.bf16.f32 %0, %1;" : "=h"(u) : "f"(f)); return u;
}
__device__ __forceinline__ float sin_ap(float x) {
    float r; asm("sin.approx.f32 %0, %1;" : "=f"(r) : "f"(x)); return r;
}
__device__ __forceinline__ float ex2_ap(float x) {
    float r; asm("ex2.approx.f32 %0, %1;" : "=f"(r) : "f"(x)); return r;
}
__device__ __forceinline__ void split2(float a, float b, uint32_t& h, uint32_t& l) {
    uint32_t ba = __float_as_uint(a), bb = __float_as_uint(b);
    h = __byte_perm(ba, bb, 0x7632);
    l = pbf2(a - __uint_as_float(ba & 0xFFFF0000u),
             b - __uint_as_float(bb & 0xFFFF0000u));
}

// ---------------- problem constants ----------------
#define Bn   16
#define Nn   2048
#define DIN  512
#define DK   10
#define NH   2
#define DH   5
#define HID  20
#define DOUT 512
#define ROWS (Bn * Nn)             // 32768
#define KZ   4

// ---------------- device scratch ----------------
__device__ uint32_t g_Qb[32][Nn][8];       // split-bf16: [0..3]=hi pairs, [4..7]=lo
__device__ uint32_t g_Kb[32][Nn][8];
__device__ unsigned short g_Vth[32][5][Nn];  // V transposed, hi plane
__device__ unsigned short g_Vtl[32][5][Nn];  // lo plane
__device__ float g_A[32][Nn][KZ][8];         // partials: a0..a4, den

// =====================================================================
// Kernel 1: QKV projection on HMMA (R11 winner, verbatim: 128 rows/block).
// =====================================================================
#define XSTR 72
#define XH_OFF 0
#define XL_OFF (128 * XSTR * 2)
#define WH_OFF (2 * 128 * XSTR * 2)
#define WL_OFF (WH_OFF + 32 * XSTR * 2)
#define SM_TOT (WL_OFF + 32 * XSTR * 2)

__global__ __launch_bounds__(256) void proj_tc(
    const float* __restrict__ x,
    const float* __restrict__ Wq, const float* __restrict__ bq,
    const float* __restrict__ Wk, const float* __restrict__ bk,
    const float* __restrict__ Wv, const float* __restrict__ bv)
{
    __shared__ __align__(16) char sm[SM_TOT];
    const uint32_t sb = smem_u32(sm);

    const int tid  = threadIdx.x;
    const int wid  = tid >> 5;
    const int lane = tid & 31;
    const int row0 = blockIdx.x * 128;
    const int m0   = wid * 16;

    float C[4][4];
#pragma unroll
    for (int t = 0; t < 4; t++)
#pragma unroll
        for (int i = 0; i < 4; i++) C[t][i] = 0.f;

    float4 xr[8];
    float  wr[8];
#pragma unroll
    for (int it = 0; it < 8; it++) {
        int e = tid + it * 256;
        int r = e >> 4, c4 = e & 15;
        xr[it] = *reinterpret_cast<const float4*>(x + (size_t)(row0 + r) * DIN + c4 * 4);
    }
#pragma unroll
    for (int it = 0; it < 8; it++) {
        int e = tid + it * 256;
        int k = e >> 5, j = e & 31;
        wr[it] = (j < 10) ? Wq[k * DK + j]
               : (j < 20) ? Wk[k * DK + (j - 10)]
               : (j < 30) ? Wv[k * DK + (j - 20)] : 0.f;
    }

    const int arow = lane & 15;
    const int agrp = lane >> 4;
    const int bn = lane >> 2;
    const int bk0 = (lane & 3) * 2;

    for (int c = 0; c < 8; c++) {
        __syncthreads();
#pragma unroll
        for (int it = 0; it < 8; it++) {
            int e = tid + it * 256;
            int r = e >> 4, c4 = e & 15;
            float4 v = xr[it];
            uint32_t h01, l01, h23, l23;
            split2(v.x, v.y, h01, l01);
            split2(v.z, v.w, h23, l23);
            uint32_t off = (r * XSTR + c4 * 4) * 2;
            *reinterpret_cast<uint2*>(sm + XH_OFF + off) = make_uint2(h01, h23);
            *reinterpret_cast<uint2*>(sm + XL_OFF + off) = make_uint2(l01, l23);
        }
#pragma unroll
        for (int it = 0; it < 8; it++) {
            int e = tid + it * 256;
            int k = e >> 5, j = e & 31;
            float w = wr[it];
            uint32_t wb = __float_as_uint(w);
            uint32_t off = (j * XSTR + k) * 2;
            *reinterpret_cast<unsigned short*>(sm + WH_OFF + off) = (unsigned short)(wb >> 16);
            *reinterpret_cast<unsigned short*>(sm + WL_OFF + off) =
                bf16rn(w - __uint_as_float(wb & 0xFFFF0000u));
        }
        __syncthreads();

        if (c < 7) {
            const int kc = (c + 1) * 64;
#pragma unroll
            for (int it = 0; it < 8; it++) {
                int e = tid + it * 256;
                int r = e >> 4, c4 = e & 15;
                xr[it] = *reinterpret_cast<const float4*>(
                    x + (size_t)(row0 + r) * DIN + kc + c4 * 4);
            }
#pragma unroll
            for (int it = 0; it < 8; it++) {
                int e = tid + it * 256;
                int k = kc + (e >> 5), j = e & 31;
                wr[it] = (j < 10) ? Wq[k * DK + j]
                       : (j < 20) ? Wk[k * DK + (j - 10)]
                       : (j < 30) ? Wv[k * DK + (j - 20)] : 0.f;
            }
        }

#pragma unroll
        for (int ks = 0; ks < 4; ks++) {
            uint32_t ah[4], al[4];
            uint32_t abase = (m0 + arow) * (XSTR * 2) + ks * 32 + agrp * 16;
            ldsm4(ah, sb + XH_OFF + abase);
            ldsm4(al, sb + XL_OFF + abase);
#pragma unroll
            for (int t = 0; t < 4; t++) {
                uint32_t boff = ((bn + t * 8) * XSTR + ks * 16 + bk0) * 2;
                uint32_t bh0 = *reinterpret_cast<const uint32_t*>(sm + WH_OFF + boff);
                uint32_t bh1 = *reinterpret_cast<const uint32_t*>(sm + WH_OFF + boff + 16);
                uint32_t bl0 = *reinterpret_cast<const uint32_t*>(sm + WL_OFF + boff);
                uint32_t bl1 = *reinterpret_cast<const uint32_t*>(sm + WL_OFF + boff + 16);
                mma_k16(C[t], ah, bh0, bh1);
                mma_k16(C[t], ah, bl0, bl1);
                mma_k16(C[t], al, bh0, bh1);
            }
        }
    }

    __syncthreads();
    float* co = reinterpret_cast<float*>(sm);
    {
        const int r_c = lane >> 2;
        const int j2  = (lane & 3) * 2;
#pragma unroll
        for (int t = 0; t < 4; t++) {
            float* p0 = co + (m0 + r_c) * 33 + t * 8 + j2;
            float* p1 = co + (m0 + r_c + 8) * 33 + t * 8 + j2;
            p0[0] = C[t][0]; p0[1] = C[t][1];
            p1[0] = C[t][2]; p1[1] = C[t][3];
        }
    }
    __syncthreads();

    if (tid < 128) {
        const float* src = co + tid * 33;
        float o[30];
#pragma unroll
        for (int j = 0; j < 30; j++) o[j] = src[j];

        const int grow = row0 + tid;
        const int b = grow >> 11, n = grow & (Nn - 1);
        const float rs = 0.4472135954999579f;   // 1/sqrt(5)

        float q[10], kk[10], vv[10];
#pragma unroll
        for (int j = 0; j < 10; j++) {
            q[j]  = (o[j]      + bq[j]) * rs;
            kk[j] = (o[j + 10] + bk[j]);
            vv[j] = (o[j + 20] + bv[j]);
        }
#pragma unroll
        for (int h = 0; h < 2; h++) {
            int bh = b * NH + h;
            uint32_t qh[4], ql[4], kh[4], kl[4];
            split2(q[h*5+0], q[h*5+1], qh[0], ql[0]);
            split2(q[h*5+2], q[h*5+3], qh[1], ql[1]);
            split2(q[h*5+4], 0.f,      qh[2], ql[2]);
            qh[3] = 0; ql[3] = 0;
            split2(kk[h*5+0], kk[h*5+1], kh[0], kl[0]);
            split2(kk[h*5+2], kk[h*5+3], kh[1], kl[1]);
            split2(kk[h*5+4], 0.f,       kh[2], kl[2]);
            kh[3] = 0; kl[3] = 0;
            *reinterpret_cast<uint4*>(&g_Qb[bh][n][0]) = make_uint4(qh[0], qh[1], qh[2], qh[3]);
            *reinterpret_cast<uint4*>(&g_Qb[bh][n][4]) = make_uint4(ql[0], ql[1], ql[2], ql[3]);
            *reinterpret_cast<uint4*>(&g_Kb[bh][n][0]) = make_uint4(kh[0], kh[1], kh[2], kh[3]);
            *reinterpret_cast<uint4*>(&g_Kb[bh][n][4]) = make_uint4(kl[0], kl[1], kl[2], kl[3]);
#pragma unroll
            for (int d = 0; d < 5; d++) {
                float v = vv[h*5+d];
                uint32_t vb = __float_as_uint(v);
                g_Vth[bh][d][n] = (unsigned short)(vb >> 16);
                g_Vtl[bh][d][n] = bf16rn(v - __uint_as_float(vb & 0xFFFF0000u));
            }
        }
    }
}

// =====================================================================
// Kernel 2: HMMA attention (R12 best config: register prefetch, KZ=4).
// =====================================================================
#define AQH 0
#define AQL 2048
#define AKH 4096
#define AKL 6144
#define AVH 8192
#define AVL (AVH + 8 * 136 * 2)       // 10368
#define AT_SM (AVL + 8 * 136 * 2)     // 12544

__global__ __launch_bounds__(256) void attn_tc()
{
    __shared__ __align__(16) char sm[AT_SM];

    const int tid  = threadIdx.x;
    const int wid  = tid >> 5;
    const int lane = tid & 31;
    const int qt   = (Nn / 128 - 1) - blockIdx.x;    // heavy tiles first
    const int bh   = blockIdx.y;
    const int kz   = blockIdx.z;
    const int m0   = wid * 16;
    const int r    = lane >> 2;
    const int j    = lane & 3;

    const int nt = qt + 1;
    const int t0 = (nt * kz) / KZ, t1 = (nt * (kz + 1)) / KZ;

    float Cpv[4] = {0.f, 0.f, 0.f, 0.f};
    const float LOG2E = 1.4426950408889634f;

    if (t0 < t1) {
        for (int e = tid; e < 3 * 136; e += 256) {
            int d = 5 + e / 136, kk2 = e % 136;
            *reinterpret_cast<unsigned short*>(sm + AVH + (d * 136 + kk2) * 2) =
                (d == 5) ? (unsigned short)0x3F80 : (unsigned short)0;
            *reinterpret_cast<unsigned short*>(sm + AVL + (d * 136 + kk2) * 2) = 0;
        }
        if (tid < 128) {
            uint4 h = *reinterpret_cast<const uint4*>(&g_Qb[bh][qt * 128 + tid][0]);
            uint4 l = *reinterpret_cast<const uint4*>(&g_Qb[bh][qt * 128 + tid][4]);
            *reinterpret_cast<uint4*>(sm + AQH + tid * 16) = h;
            *reinterpret_cast<uint4*>(sm + AQL + tid * 16) = l;
        }
        __syncthreads();

        uint32_t qh0, qh1, ql0, ql1;
        {
            uint32_t w0 = (m0 + r) * 16 + j * 4;
            uint32_t w1 = (m0 + r + 8) * 16 + j * 4;
            qh0 = *reinterpret_cast<const uint32_t*>(sm + AQH + w0);
            qh1 = *reinterpret_cast<const uint32_t*>(sm + AQH + w1);
            ql0 = *reinterpret_cast<const uint32_t*>(sm + AQL + w0);
            ql1 = *reinterpret_cast<const uint32_t*>(sm + AQL + w1);
        }

        uint32_t vr[5];
        uint4 kh4, kl4;
        const int key = tid & 127;

        {
            const int key0 = t0 * 128;
            if (tid < 128) {
#pragma unroll
                for (int it = 0; it < 5; it++) {
                    int e = tid + it * 128;
                    int pl = e / 320, rem = e % 320;
                    int d = rem >> 6, kp = rem & 63;
                    vr[it] = pl
                        ? *reinterpret_cast<const uint32_t*>(&g_Vtl[bh][d][key0 + 2 * kp])
                        : *reinterpret_cast<const uint32_t*>(&g_Vth[bh][d][key0 + 2 * kp]);
                }
            } else {
                kh4 = *reinterpret_cast<const uint4*>(&g_Kb[bh][key0 + key][0]);
                kl4 = *reinterpret_cast<const uint4*>(&g_Kb[bh][key0 + key][4]);
            }
        }

        for (int ck = t0; ck < t1; ck++) {
            __syncthreads();
            if (tid < 128) {
#pragma unroll
                for (int it = 0; it < 5; it++) {
                    int e = tid + it * 128;
                    int pl = e / 320, rem = e % 320;
                    int d = rem >> 6, kp = rem & 63;
                    *reinterpret_cast<uint32_t*>(
                        sm + (pl ? AVL : AVH) + (d * 136 + 2 * kp) * 2) = vr[it];
                }
            } else {
                *reinterpret_cast<uint4*>(sm + AKH + key * 16) = kh4;
                *reinterpret_cast<uint4*>(sm + AKL + key * 16) = kl4;
            }
            __syncthreads();

            if (ck + 1 < t1) {
                const int key0 = (ck + 1) * 128;
                if (tid < 128) {
#pragma unroll
                    for (int it = 0; it < 5; it++) {
                        int e = tid + it * 128;
                        int pl = e / 320, rem = e % 320;
                        int d = rem >> 6, kp = rem & 63;
                        vr[it] = pl
                            ? *reinterpret_cast<const uint32_t*>(&g_Vtl[bh][d][key0 + 2 * kp])
                            : *reinterpret_cast<const uint32_t*>(&g_Vth[bh][d][key0 + 2 * kp]);
                    }
                } else {
                    kh4 = *reinterpret_cast<const uint4*>(&g_Kb[bh][key0 + key][0]);
                    kl4 = *reinterpret_cast<const uint4*>(&g_Kb[bh][key0 + key][4]);
                }
            }

            const bool diag = (ck == qt);

#pragma unroll 2
            for (int ks = 0; ks < 8; ks++) {
                const int kbase = ks * 16;
                if (diag && kbase > m0 + 15) break;
                const bool needMask = diag && (kbase + 15 > m0);

                float c0[4] = {0.f,0.f,0.f,0.f}, c1[4] = {0.f,0.f,0.f,0.f};
                {
                    uint32_t o0 = (kbase + r) * 16 + j * 4;
                    uint32_t o1 = (kbase + 8 + r) * 16 + j * 4;
                    uint32_t b0h = *reinterpret_cast<const uint32_t*>(sm + AKH + o0);
                    uint32_t b0l = *reinterpret_cast<const uint32_t*>(sm + AKL + o0);
                    uint32_t b1h = *reinterpret_cast<const uint32_t*>(sm + AKH + o1);
                    uint32_t b1l = *reinterpret_cast<const uint32_t*>(sm + AKL + o1);
                    mma_k8(c0, qh0, qh1, b0h);
                    mma_k8(c0, qh0, qh1, b0l);
                    mma_k8(c0, ql0, ql1, b0h);
                    mma_k8(c1, qh0, qh1, b1h);
                    mma_k8(c1, qh0, qh1, b1l);
                    mma_k8(c1, ql0, ql1, b1h);
                }

                float p[8];
#pragma unroll
                for (int i = 0; i < 4; i++) p[i]     = ex2_ap(sin_ap(c0[i]) * LOG2E);
#pragma unroll
                for (int i = 0; i < 4; i++) p[4 + i] = ex2_ap(sin_ap(c1[i]) * LOG2E);

                if (needMask) {
                    int q_lo = m0 + r, q_hi = q_lo + 8;
                    int k00 = kbase + 2 * j, k01 = k00 + 1;
                    int k10 = k00 + 8,       k11 = k01 + 8;
                    p[0] = (k00 <= q_lo) ? p[0] : 0.f;
                    p[1] = (k01 <= q_lo) ? p[1] : 0.f;
                    p[2] = (k00 <= q_hi) ? p[2] : 0.f;
                    p[3] = (k01 <= q_hi) ? p[3] : 0.f;
                    p[4] = (k10 <= q_lo) ? p[4] : 0.f;
                    p[5] = (k11 <= q_lo) ? p[5] : 0.f;
                    p[6] = (k10 <= q_hi) ? p[6] : 0.f;
                    p[7] = (k11 <= q_hi) ? p[7] : 0.f;
                }

                uint32_t ah[4], al[4];
#pragma unroll
                for (int i = 0; i < 4; i++) {
                    uint32_t h = pbf2(p[2*i], p[2*i+1]);
                    ah[i] = h;
                    float r0 = __uint_as_float(h << 16);
                    float r1 = __uint_as_float(h & 0xFFFF0000u);
                    al[i] = pbf2(p[2*i] - r0, p[2*i+1] - r1);
                }

                uint32_t vo = (r * 136 + kbase + 2 * j) * 2;
                uint32_t bvh0 = *reinterpret_cast<const uint32_t*>(sm + AVH + vo);
                uint32_t bvh1 = *reinterpret_cast<const uint32_t*>(sm + AVH + vo + 16);
                uint32_t bvl0 = *reinterpret_cast<const uint32_t*>(sm + AVL + vo);
                uint32_t bvl1 = *reinterpret_cast<const uint32_t*>(sm + AVL + vo + 16);

                mma_k16(Cpv, ah, bvh0, bvh1);
                mma_k16(Cpv, ah, bvl0, bvl1);
                mma_k16(Cpv, al, bvh0, bvh1);
            }
        }
    }

    if (j < 3) {
        int q1 = qt * 128 + m0 + r;
        *reinterpret_cast<float2*>(&g_A[bh][q1][kz][2 * j]) = make_float2(Cpv[0], Cpv[1]);
        int q2 = q1 + 8;
        *reinterpret_cast<float2*>(&g_A[bh][q2][kz][2 * j]) = make_float2(Cpv[2], Cpv[3]);
    }
}

// =====================================================================
// Kernel 3: combine partials + MLP head on HMMA, COLUMN-SPLIT x2.
// Grid (256, 2): blockIdx.y picks output-column half (256 cols).
// Per block: stage only its 2 nc chunks of Wm2 -> total staging unchanged,
// occupancy doubled. h1/combine duplicated (trivial).
// =====================================================================
#define MA_H 0
#define MA_L (128 * 40 * 2)
#define MB_H (2 * 128 * 40 * 2)
#define MB_L (MB_H + 128 * 36 * 2)
#define MCS  (MB_L + 128 * 36 * 2)
#define MBM2 (MCS + 128 * 10 * 4)
#define MLP_SM (MBM2 + 256 * 4)

__global__ __launch_bounds__(256) void mlp_tc(
    const float* __restrict__ Wm1, const float* __restrict__ bm1,
    const float* __restrict__ Wm2, const float* __restrict__ bm2,
    float* __restrict__ out)
{
    __shared__ __align__(16) char sm[MLP_SM];
    const uint32_t sb = smem_u32(sm);

    const int tid  = threadIdx.x;
    const int wid  = tid >> 5;
    const int lane = tid & 31;
    const int row0 = blockIdx.x * 128;
    const int colh = blockIdx.y;             // column half: 0 or 1
    const int ncol0 = colh * 256;
    const int m0   = wid * 16;

    float* cs   = reinterpret_cast<float*>(sm + MCS);
    float* bm2s = reinterpret_cast<float*>(sm + MBM2);

    for (int e = tid; e < 128 * 10; e += 256) {
        int r = e / 10, k = e % 10;
        int h = k / DH, d = k % DH;
        int grow = row0 + r;
        int b = grow >> 11, n = grow & (Nn - 1);
        const float* A = g_A[b * NH + h][n][0];
        float den = 0.f, num = 0.f;
#pragma unroll
        for (int s = 0; s < KZ; s++) {
            num += A[8 * s + d];
            den += A[8 * s + 5];
        }
        cs[e] = num * __fdividef(1.f, den);
    }
    for (int e = tid; e < 256; e += 256) bm2s[e] = bm2[ncol0 + e];
    __syncthreads();

    for (int e = tid; e < 128 * 12; e += 256) {
        int r = e / 12, k = 20 + e % 12;
        *reinterpret_cast<unsigned short*>(sm + MA_H + (r * 40 + k) * 2) = 0;
        *reinterpret_cast<unsigned short*>(sm + MA_L + (r * 40 + k) * 2) = 0;
    }
    for (int e = tid; e < 128 * HID; e += 256) {
        int r = e / HID, jj = e % HID;
        const float* crow = cs + r * 10;
        float s = bm1[jj];
#pragma unroll
        for (int k = 0; k < DK; k++)
            s = fmaf(crow[k], Wm1[k * HID + jj], s);
        s = (s > 0.f) ? s : 0.01f * s;
        uint32_t bits = __float_as_uint(s);
        *reinterpret_cast<unsigned short*>(sm + MA_H + (r * 40 + jj) * 2) =
            (unsigned short)(bits >> 16);
        *reinterpret_cast<unsigned short*>(sm + MA_L + (r * 40 + jj) * 2) =
            bf16rn(s - __uint_as_float(bits & 0xFFFF0000u));
    }
    __syncthreads();

    const int arow = lane & 15;
    const int agrp = lane >> 4;
    uint32_t ah[2][4], al[2][4];
#pragma unroll
    for (int ks = 0; ks < 2; ks++) {
        uint32_t abase = (m0 + arow) * 80 + ks * 32 + agrp * 16;
        ldsm4(ah[ks], sb + MA_H + abase);
        ldsm4(al[ks], sb + MA_L + abase);
    }

    const int bn = lane >> 2;
    const int bj = (lane & 3) * 2;
    const int rC = lane >> 2;
    const int jC = lane & 3;

#pragma unroll
    for (int nci = 0; nci < 2; nci++) {
        const int nc = colh * 2 + nci;
        __syncthreads();
        for (int e = tid; e < 128 * 32; e += 256) {
            int k = e >> 7, nl = e & 127;
            float w = (k < HID) ? Wm2[k * DOUT + nc * 128 + nl] : 0.f;
            uint32_t wb = __float_as_uint(w);
            *reinterpret_cast<unsigned short*>(sm + MB_H + (nl * 36 + k) * 2) =
                (unsigned short)(wb >> 16);
            *reinterpret_cast<unsigned short*>(sm + MB_L + (nl * 36 + k) * 2) =
                bf16rn(w - __uint_as_float(wb & 0xFFFF0000u));
        }
        __syncthreads();

#pragma unroll 4
        for (int t = 0; t < 16; t++) {
            float C[4] = {0.f, 0.f, 0.f, 0.f};
#pragma unroll
            for (int ks = 0; ks < 2; ks++) {
                uint32_t bo = ((bn + t * 8) * 36 + ks * 16 + bj) * 2;
                uint32_t bh0 = *reinterpret_cast<const uint32_t*>(sm + MB_H + bo);
                uint32_t bh1 = *reinterpret_cast<const uint32_t*>(sm + MB_H + bo + 16);
                uint32_t bl0 = *reinterpret_cast<const uint32_t*>(sm + MB_L + bo);
                uint32_t bl1 = *reinterpret_cast<const uint32_t*>(sm + MB_L + bo + 16);
                mma_k16(C, ah[ks], bh0, bh1);
                mma_k16(C, ah[ks], bl0, bl1);
                mma_k16(C, al[ks], bh0, bh1);
            }
            int n0 = nc * 128 + t * 8;
            int nb = n0 - ncol0;
            float b0 = bm2s[nb + 2 * jC], b1 = bm2s[nb + 2 * jC + 1];
            size_t ro = (size_t)(row0 + m0 + rC) * DOUT + n0 + 2 * jC;
            *reinterpret_cast<float2*>(out + ro) = make_float2(C[0] + b0, C[1] + b1);
            *reinterpret_cast<float2*>(out + ro + 8 * DOUT) = make_float2(C[2] + b0, C[3] + b1);
        }
    }
}

// =====================================================================
extern "C" void kernel_launch(void* const* d_in, const int* in_sizes, int n_in,
                              void* d_out, int out_size)
{
    const float* x   = (const float*)d_in[0];
    const float* Wq  = (const float*)d_in[1];
    const float* bq  = (const float*)d_in[2];
    const float* Wk  = (const float*)d_in[3];
    const float* bk  = (const float*)d_in[4];
    const float* Wv  = (const float*)d_in[5];
    const float* bv  = (const float*)d_in[6];
    const float* Wm1 = (const float*)d_in[7];
    const float* bm1 = (const float*)d_in[8];
    const float* Wm2 = (const float*)d_in[9];
    const float* bm2 = (const float*)d_in[10];

    proj_tc<<<ROWS / 128, 256>>>(x, Wq, bq, Wk, bk, Wv, bv);
    attn_tc<<<dim3(Nn / 128, 32, KZ), 256>>>();
    mlp_tc<<<dim3(ROWS / 128, 2), 256>>>(Wm1, bm1, Wm2, bm2, (float*)d_out);
}

// round 16
// speedup vs baseline: 1.3199x; 1.2334x over previous
#include <cuda_runtime.h>
#include <cuda_bf16.h>
#include <cstdint>

// ---------------- HMMA / misc helpers (family-portable: sm_80+) ----------------
__device__ __forceinline__ uint32_t smem_u32(const void* p) {
    uint32_t a;
    asm("{ .reg .u64 t; cvta.to.shared.u64 t, %1; cvt.u32.u64 %0, t; }" : "=r"(a) : "l"(p));
    return a;
}
__device__ __forceinline__ void ldsm4(uint32_t r[4], uint32_t addr) {
    asm volatile("ldmatrix.sync.aligned.m8n8.x4.shared.b16 {%0,%1,%2,%3}, [%4];"
        : "=r"(r[0]), "=r"(r[1]), "=r"(r[2]), "=r"(r[3]) : "r"(addr));
}
__device__ __forceinline__ void mma_k16(float c[4], const uint32_t a[4], uint32_t b0, uint32_t b1) {
    asm volatile("mma.sync.aligned.m16n8k16.row.col.f32.bf16.bf16.f32 "
        "{%0,%1,%2,%3}, {%4,%5,%6,%7}, {%8,%9}, {%0,%1,%2,%3};"
        : "+f"(c[0]), "+f"(c[1]), "+f"(c[2]), "+f"(c[3])
        : "r"(a[0]), "r"(a[1]), "r"(a[2]), "r"(a[3]), "r"(b0), "r"(b1));
}
__device__ __forceinline__ void mma_k8(float c[4], uint32_t a0, uint32_t a1, uint32_t b0) {
    asm volatile("mma.sync.aligned.m16n8k8.row.col.f32.bf16.bf16.f32 "
        "{%0,%1,%2,%3}, {%4,%5}, {%6}, {%0,%1,%2,%3};"
        : "+f"(c[0]), "+f"(c[1]), "+f"(c[2]), "+f"(c[3])
        : "r"(a0), "r"(a1), "r"(b0));
}
__device__ __forceinline__ uint32_t pbf2(float lo, float hi) {   // low half = lo
    uint32_t r; asm("cvt.rn.bf16x2.f32 %0, %1, %2;" : "=r"(r) : "f"(hi), "f"(lo)); return r;
}
__device__ __forceinline__ unsigned short bf16rn(float f) {
    unsigned short u; asm("cvt.rn.bf16.f32 %0, %1;" : "=h"(u) : "f"(f)); return u;
}
__device__ __forceinline__ float sin_ap(float x) {
    float r; asm("sin.approx.f32 %0, %1;" : "=f"(r) : "f"(x)); return r;
}
__device__ __forceinline__ float ex2_ap(float x) {
    float r; asm("ex2.approx.f32 %0, %1;" : "=f"(r) : "f"(x)); return r;
}
__device__ __forceinline__ void split2(float a, float b, uint32_t& h, uint32_t& l) {
    uint32_t ba = __float_as_uint(a), bb = __float_as_uint(b);
    h = __byte_perm(ba, bb, 0x7632);
    l = pbf2(a - __uint_as_float(ba & 0xFFFF0000u),
             b - __uint_as_float(bb & 0xFFFF0000u));
}

// ---------------- problem constants ----------------
#define Bn   16
#define Nn   2048
#define DIN  512
#define DK   10
#define NH   2
#define DH   5
#define HID  20
#define DOUT 512
#define ROWS (Bn * Nn)             // 32768
#define KZ   4

// ---------------- device scratch ----------------
__device__ uint32_t g_Qb[32][Nn][8];       // split-bf16: [0..3]=hi pairs, [4..7]=lo
__device__ uint32_t g_Kb[32][Nn][8];
__device__ unsigned short g_Vth[32][5][Nn];  // V transposed, hi plane
__device__ unsigned short g_Vtl[32][5][Nn];  // lo plane
__device__ float g_A[32][Nn][KZ][8];         // partials: a0..a4, den
// precomputed split-bf16 weights
__device__ __align__(16) unsigned short g_Wph[32][512];  // qkv W: [j][k] hi
__device__ __align__(16) unsigned short g_Wpl[32][512];  // lo
__device__ __align__(16) unsigned short g_W2h[512][40];  // Wm2: [n][k pad40] hi
__device__ __align__(16) unsigned short g_W2l[512][40];  // lo

// =====================================================================
// Kernel 0: one-time weight split-bf16 prep (W qkv + Wm2).
// =====================================================================
__global__ __launch_bounds__(256) void prep(
    const float* __restrict__ Wq, const float* __restrict__ Wk,
    const float* __restrict__ Wv, const float* __restrict__ Wm2)
{
    int idx = blockIdx.x * 256 + threadIdx.x;
    if (idx < 32 * 512) {
        int j = idx >> 9, k = idx & 511;
        float w = (j < 10) ? Wq[k * DK + j]
                : (j < 20) ? Wk[k * DK + (j - 10)]
                : (j < 30) ? Wv[k * DK + (j - 20)] : 0.f;
        uint32_t wb = __float_as_uint(w);
        g_Wph[j][k] = (unsigned short)(wb >> 16);
        g_Wpl[j][k] = bf16rn(w - __uint_as_float(wb & 0xFFFF0000u));
    } else if (idx < 32 * 512 + 512 * 40) {
        int e = idx - 32 * 512;
        int col = e / 40, k = e % 40;
        float w = (k < HID) ? Wm2[k * DOUT + col] : 0.f;
        uint32_t wb = __float_as_uint(w);
        g_W2h[col][k] = (unsigned short)(wb >> 16);
        g_W2l[col][k] = bf16rn(w - __uint_as_float(wb & 0xFFFF0000u));
    }
}

// =====================================================================
// Kernel 1: QKV projection on HMMA (R11 topology; W staging = pure copies).
// =====================================================================
#define XSTR 72
#define XH_OFF 0
#define XL_OFF (128 * XSTR * 2)
#define WH_OFF (2 * 128 * XSTR * 2)
#define WL_OFF (WH_OFF + 32 * XSTR * 2)
#define SM_TOT (WL_OFF + 32 * XSTR * 2)

__global__ __launch_bounds__(256) void proj_tc(
    const float* __restrict__ x,
    const float* __restrict__ bq, const float* __restrict__ bk,
    const float* __restrict__ bv)
{
    __shared__ __align__(16) char sm[SM_TOT];
    const uint32_t sb = smem_u32(sm);

    const int tid  = threadIdx.x;
    const int wid  = tid >> 5;
    const int lane = tid & 31;
    const int row0 = blockIdx.x * 128;
    const int m0   = wid * 16;

    float C[4][4];
#pragma unroll
    for (int t = 0; t < 4; t++)
#pragma unroll
        for (int i = 0; i < 4; i++) C[t][i] = 0.f;

    // W copy mapping (fixed per thread): 512 uint4 = 2/thread
    const int wpl0 = tid >> 8;                    // always 0 for it=0.. compute per it
    float4 xr[8];
    uint4  wr4[2];
#pragma unroll
    for (int it = 0; it < 8; it++) {
        int e = tid + it * 256;
        int r = e >> 4, c4 = e & 15;
        xr[it] = *reinterpret_cast<const float4*>(x + (size_t)(row0 + r) * DIN + c4 * 4);
    }
#pragma unroll
    for (int it = 0; it < 2; it++) {
        int e = tid + it * 256;
        int pl = e >> 8, rem = e & 255;
        int j = rem >> 3, q = rem & 7;
        const unsigned short* srcp = pl ? &g_Wpl[j][q * 8] : &g_Wph[j][q * 8];
        wr4[it] = *reinterpret_cast<const uint4*>(srcp);
    }
    (void)wpl0;

    const int arow = lane & 15;
    const int agrp = lane >> 4;
    const int bn = lane >> 2;
    const int bk0 = (lane & 3) * 2;

    for (int c = 0; c < 8; c++) {
        __syncthreads();
#pragma unroll
        for (int it = 0; it < 8; it++) {
            int e = tid + it * 256;
            int r = e >> 4, c4 = e & 15;
            float4 v = xr[it];
            uint32_t h01, l01, h23, l23;
            split2(v.x, v.y, h01, l01);
            split2(v.z, v.w, h23, l23);
            uint32_t off = (r * XSTR + c4 * 4) * 2;
            *reinterpret_cast<uint2*>(sm + XH_OFF + off) = make_uint2(h01, h23);
            *reinterpret_cast<uint2*>(sm + XL_OFF + off) = make_uint2(l01, l23);
        }
#pragma unroll
        for (int it = 0; it < 2; it++) {
            int e = tid + it * 256;
            int pl = e >> 8, rem = e & 255;
            int j = rem >> 3, q = rem & 7;
            *reinterpret_cast<uint4*>(
                sm + (pl ? WL_OFF : WH_OFF) + (j * XSTR + q * 8) * 2) = wr4[it];
        }
        __syncthreads();

        if (c < 7) {
            const int kc = (c + 1) * 64;
#pragma unroll
            for (int it = 0; it < 8; it++) {
                int e = tid + it * 256;
                int r = e >> 4, c4 = e & 15;
                xr[it] = *reinterpret_cast<const float4*>(
                    x + (size_t)(row0 + r) * DIN + kc + c4 * 4);
            }
#pragma unroll
            for (int it = 0; it < 2; it++) {
                int e = tid + it * 256;
                int pl = e >> 8, rem = e & 255;
                int j = rem >> 3, q = rem & 7;
                const unsigned short* srcp = pl ? &g_Wpl[j][kc + q * 8] : &g_Wph[j][kc + q * 8];
                wr4[it] = *reinterpret_cast<const uint4*>(srcp);
            }
        }

#pragma unroll
        for (int ks = 0; ks < 4; ks++) {
            uint32_t ah[4], al[4];
            uint32_t abase = (m0 + arow) * (XSTR * 2) + ks * 32 + agrp * 16;
            ldsm4(ah, sb + XH_OFF + abase);
            ldsm4(al, sb + XL_OFF + abase);
#pragma unroll
            for (int t = 0; t < 4; t++) {
                uint32_t boff = ((bn + t * 8) * XSTR + ks * 16 + bk0) * 2;
                uint32_t bh0 = *reinterpret_cast<const uint32_t*>(sm + WH_OFF + boff);
                uint32_t bh1 = *reinterpret_cast<const uint32_t*>(sm + WH_OFF + boff + 16);
                uint32_t bl0 = *reinterpret_cast<const uint32_t*>(sm + WL_OFF + boff);
                uint32_t bl1 = *reinterpret_cast<const uint32_t*>(sm + WL_OFF + boff + 16);
                mma_k16(C[t], ah, bh0, bh1);
                mma_k16(C[t], ah, bl0, bl1);
                mma_k16(C[t], al, bh0, bh1);
            }
        }
    }

    __syncthreads();
    float* co = reinterpret_cast<float*>(sm);
    {
        const int r_c = lane >> 2;
        const int j2  = (lane & 3) * 2;
#pragma unroll
        for (int t = 0; t < 4; t++) {
            float* p0 = co + (m0 + r_c) * 33 + t * 8 + j2;
            float* p1 = co + (m0 + r_c + 8) * 33 + t * 8 + j2;
            p0[0] = C[t][0]; p0[1] = C[t][1];
            p1[0] = C[t][2]; p1[1] = C[t][3];
        }
    }
    __syncthreads();

    if (tid < 128) {
        const float* src = co + tid * 33;
        float o[30];
#pragma unroll
        for (int j = 0; j < 30; j++) o[j] = src[j];

        const int grow = row0 + tid;
        const int b = grow >> 11, n = grow & (Nn - 1);
        const float rs = 0.4472135954999579f;   // 1/sqrt(5)

        float q[10], kk[10], vv[10];
#pragma unroll
        for (int j = 0; j < 10; j++) {
            q[j]  = (o[j]      + bq[j]) * rs;
            kk[j] = (o[j + 10] + bk[j]);
            vv[j] = (o[j + 20] + bv[j]);
        }
#pragma unroll
        for (int h = 0; h < 2; h++) {
            int bh = b * NH + h;
            uint32_t qh[4], ql[4], kh[4], kl[4];
            split2(q[h*5+0], q[h*5+1], qh[0], ql[0]);
            split2(q[h*5+2], q[h*5+3], qh[1], ql[1]);
            split2(q[h*5+4], 0.f,      qh[2], ql[2]);
            qh[3] = 0; ql[3] = 0;
            split2(kk[h*5+0], kk[h*5+1], kh[0], kl[0]);
            split2(kk[h*5+2], kk[h*5+3], kh[1], kl[1]);
            split2(kk[h*5+4], 0.f,       kh[2], kl[2]);
            kh[3] = 0; kl[3] = 0;
            *reinterpret_cast<uint4*>(&g_Qb[bh][n][0]) = make_uint4(qh[0], qh[1], qh[2], qh[3]);
            *reinterpret_cast<uint4*>(&g_Qb[bh][n][4]) = make_uint4(ql[0], ql[1], ql[2], ql[3]);
            *reinterpret_cast<uint4*>(&g_Kb[bh][n][0]) = make_uint4(kh[0], kh[1], kh[2], kh[3]);
            *reinterpret_cast<uint4*>(&g_Kb[bh][n][4]) = make_uint4(kl[0], kl[1], kl[2], kl[3]);
#pragma unroll
            for (int d = 0; d < 5; d++) {
                float v = vv[h*5+d];
                uint32_t vb = __float_as_uint(v);
                g_Vth[bh][d][n] = (unsigned short)(vb >> 16);
                g_Vtl[bh][d][n] = bf16rn(v - __uint_as_float(vb & 0xFFFF0000u));
            }
        }
    }
}

// =====================================================================
// Kernel 2: HMMA attention (R12 config) + S-mma merge:
// Qh*Kh + Ql*Kh in ONE k16 mma (A=[Qh|Ql], B=[Kh|Kh]) + k8 Qh*Kl.
// =====================================================================
#define AQH 0
#define AQL 2048
#define AKH 4096
#define AKL 6144
#define AVH 8192
#define AVL (AVH + 8 * 136 * 2)       // 10368
#define AT_SM (AVL + 8 * 136 * 2)     // 12544

__global__ __launch_bounds__(256) void attn_tc()
{
    __shared__ __align__(16) char sm[AT_SM];

    const int tid  = threadIdx.x;
    const int wid  = tid >> 5;
    const int lane = tid & 31;
    const int qt   = (Nn / 128 - 1) - blockIdx.x;    // heavy tiles first
    const int bh   = blockIdx.y;
    const int kz   = blockIdx.z;
    const int m0   = wid * 16;
    const int r    = lane >> 2;
    const int j    = lane & 3;

    const int nt = qt + 1;
    const int t0 = (nt * kz) / KZ, t1 = (nt * (kz + 1)) / KZ;

    float Cpv[4] = {0.f, 0.f, 0.f, 0.f};
    const float LOG2E = 1.4426950408889634f;

    if (t0 < t1) {
        for (int e = tid; e < 3 * 136; e += 256) {
            int d = 5 + e / 136, kk2 = e % 136;
            *reinterpret_cast<unsigned short*>(sm + AVH + (d * 136 + kk2) * 2) =
                (d == 5) ? (unsigned short)0x3F80 : (unsigned short)0;
            *reinterpret_cast<unsigned short*>(sm + AVL + (d * 136 + kk2) * 2) = 0;
        }
        if (tid < 128) {
            uint4 h = *reinterpret_cast<const uint4*>(&g_Qb[bh][qt * 128 + tid][0]);
            uint4 l = *reinterpret_cast<const uint4*>(&g_Qb[bh][qt * 128 + tid][4]);
            *reinterpret_cast<uint4*>(sm + AQH + tid * 16) = h;
            *reinterpret_cast<uint4*>(sm + AQL + tid * 16) = l;
        }
        __syncthreads();

        uint32_t Aq[4];   // [Qh(k0-7) | Ql(k8-15)] merged A-frag
        uint32_t qh0, qh1;
        {
            uint32_t w0 = (m0 + r) * 16 + j * 4;
            uint32_t w1 = (m0 + r + 8) * 16 + j * 4;
            qh0 = *reinterpret_cast<const uint32_t*>(sm + AQH + w0);
            qh1 = *reinterpret_cast<const uint32_t*>(sm + AQH + w1);
            Aq[0] = qh0;
            Aq[1] = qh1;
            Aq[2] = *reinterpret_cast<const uint32_t*>(sm + AQL + w0);
            Aq[3] = *reinterpret_cast<const uint32_t*>(sm + AQL + w1);
        }

        uint32_t vr[5];
        uint4 kh4, kl4;
        const int key = tid & 127;

        {
            const int key0 = t0 * 128;
            if (tid < 128) {
#pragma unroll
                for (int it = 0; it < 5; it++) {
                    int e = tid + it * 128;
                    int pl = e / 320, rem = e % 320;
                    int d = rem >> 6, kp = rem & 63;
                    vr[it] = pl
                        ? *reinterpret_cast<const uint32_t*>(&g_Vtl[bh][d][key0 + 2 * kp])
                        : *reinterpret_cast<const uint32_t*>(&g_Vth[bh][d][key0 + 2 * kp]);
                }
            } else {
                kh4 = *reinterpret_cast<const uint4*>(&g_Kb[bh][key0 + key][0]);
                kl4 = *reinterpret_cast<const uint4*>(&g_Kb[bh][key0 + key][4]);
            }
        }

        for (int ck = t0; ck < t1; ck++) {
            __syncthreads();
            if (tid < 128) {
#pragma unroll
                for (int it = 0; it < 5; it++) {
                    int e = tid + it * 128;
                    int pl = e / 320, rem = e % 320;
                    int d = rem >> 6, kp = rem & 63;
                    *reinterpret_cast<uint32_t*>(
                        sm + (pl ? AVL : AVH) + (d * 136 + 2 * kp) * 2) = vr[it];
                }
            } else {
                *reinterpret_cast<uint4*>(sm + AKH + key * 16) = kh4;
                *reinterpret_cast<uint4*>(sm + AKL + key * 16) = kl4;
            }
            __syncthreads();

            if (ck + 1 < t1) {
                const int key0 = (ck + 1) * 128;
                if (tid < 128) {
#pragma unroll
                    for (int it = 0; it < 5; it++) {
                        int e = tid + it * 128;
                        int pl = e / 320, rem = e % 320;
                        int d = rem >> 6, kp = rem & 63;
                        vr[it] = pl
                            ? *reinterpret_cast<const uint32_t*>(&g_Vtl[bh][d][key0 + 2 * kp])
                            : *reinterpret_cast<const uint32_t*>(&g_Vth[bh][d][key0 + 2 * kp]);
                    }
                } else {
                    kh4 = *reinterpret_cast<const uint4*>(&g_Kb[bh][key0 + key][0]);
                    kl4 = *reinterpret_cast<const uint4*>(&g_Kb[bh][key0 + key][4]);
                }
            }

            const bool diag = (ck == qt);

#pragma unroll 2
            for (int ks = 0; ks < 8; ks++) {
                const int kbase = ks * 16;
                if (diag && kbase > m0 + 15) break;
                const bool needMask = diag && (kbase + 15 > m0);

                float c0[4] = {0.f,0.f,0.f,0.f}, c1[4] = {0.f,0.f,0.f,0.f};
                {
                    uint32_t o0 = (kbase + r) * 16 + j * 4;
                    uint32_t o1 = (kbase + 8 + r) * 16 + j * 4;
                    uint32_t b0h = *reinterpret_cast<const uint32_t*>(sm + AKH + o0);
                    uint32_t b0l = *reinterpret_cast<const uint32_t*>(sm + AKL + o0);
                    uint32_t b1h = *reinterpret_cast<const uint32_t*>(sm + AKH + o1);
                    uint32_t b1l = *reinterpret_cast<const uint32_t*>(sm + AKL + o1);
                    mma_k16(c0, Aq, b0h, b0h);     // Qh*Kh + Ql*Kh
                    mma_k8(c0, qh0, qh1, b0l);     // Qh*Kl
                    mma_k16(c1, Aq, b1h, b1h);
                    mma_k8(c1, qh0, qh1, b1l);
                }

                float p[8];
#pragma unroll
                for (int i = 0; i < 4; i++) p[i]     = ex2_ap(sin_ap(c0[i]) * LOG2E);
#pragma unroll
                for (int i = 0; i < 4; i++) p[4 + i] = ex2_ap(sin_ap(c1[i]) * LOG2E);

                if (needMask) {
                    int q_lo = m0 + r, q_hi = q_lo + 8;
                    int k00 = kbase + 2 * j, k01 = k00 + 1;
                    int k10 = k00 + 8,       k11 = k01 + 8;
                    p[0] = (k00 <= q_lo) ? p[0] : 0.f;
                    p[1] = (k01 <= q_lo) ? p[1] : 0.f;
                    p[2] = (k00 <= q_hi) ? p[2] : 0.f;
                    p[3] = (k01 <= q_hi) ? p[3] : 0.f;
                    p[4] = (k10 <= q_lo) ? p[4] : 0.f;
                    p[5] = (k11 <= q_lo) ? p[5] : 0.f;
                    p[6] = (k10 <= q_hi) ? p[6] : 0.f;
                    p[7] = (k11 <= q_hi) ? p[7] : 0.f;
                }

                uint32_t ah[4], al[4];
#pragma unroll
                for (int i = 0; i < 4; i++) {
                    uint32_t h = pbf2(p[2*i], p[2*i+1]);
                    ah[i] = h;
                    float r0 = __uint_as_float(h << 16);
                    float r1 = __uint_as_float(h & 0xFFFF0000u);
                    al[i] = pbf2(p[2*i] - r0, p[2*i+1] - r1);
                }

                uint32_t vo = (r * 136 + kbase + 2 * j) * 2;
                uint32_t bvh0 = *reinterpret_cast<const uint32_t*>(sm + AVH + vo);
                uint32_t bvh1 = *reinterpret_cast<const uint32_t*>(sm + AVH + vo + 16);
                uint32_t bvl0 = *reinterpret_cast<const uint32_t*>(sm + AVL + vo);
                uint32_t bvl1 = *reinterpret_cast<const uint32_t*>(sm + AVL + vo + 16);

                mma_k16(Cpv, ah, bvh0, bvh1);
                mma_k16(Cpv, ah, bvl0, bvl1);
                mma_k16(Cpv, al, bvh0, bvh1);
            }
        }
    }

    if (j < 3) {
        int q1 = qt * 128 + m0 + r;
        *reinterpret_cast<float2*>(&g_A[bh][q1][kz][2 * j]) = make_float2(Cpv[0], Cpv[1]);
        int q2 = q1 + 8;
        *reinterpret_cast<float2*>(&g_A[bh][q2][kz][2 * j]) = make_float2(Cpv[2], Cpv[3]);
    }
}

// =====================================================================
// Kernel 3: combine partials + MLP head on HMMA (unsplit grid 256);
// Wm2 staging = pure uint4 copies of precomputed planes; B stride 40.
// =====================================================================
#define MA_H 0
#define MA_L 10240
#define MB_H 20480
#define MB_L 30720
#define MCS  40960
#define MBM2 46080
#define MLP_SM (MBM2 + 512 * 4)    // 48128

__global__ __launch_bounds__(256) void mlp_tc(
    const float* __restrict__ Wm1, const float* __restrict__ bm1,
    const float* __restrict__ bm2,
    float* __restrict__ out)
{
    __shared__ __align__(16) char sm[MLP_SM];
    const uint32_t sb = smem_u32(sm);

    const int tid  = threadIdx.x;
    const int wid  = tid >> 5;
    const int lane = tid & 31;
    const int row0 = blockIdx.x * 128;
    const int m0   = wid * 16;

    float* cs   = reinterpret_cast<float*>(sm + MCS);
    float* bm2s = reinterpret_cast<float*>(sm + MBM2);

    for (int e = tid; e < 128 * 10; e += 256) {
        int r = e / 10, k = e % 10;
        int h = k / DH, d = k % DH;
        int grow = row0 + r;
        int b = grow >> 11, n = grow & (Nn - 1);
        const float* A = g_A[b * NH + h][n][0];
        float den = 0.f, num = 0.f;
#pragma unroll
        for (int s = 0; s < KZ; s++) {
            num += A[8 * s + d];
            den += A[8 * s + 5];
        }
        cs[e] = num * __fdividef(1.f, den);
    }
    for (int e = tid; e < 512; e += 256) bm2s[e] = bm2[e];
    __syncthreads();

    for (int e = tid; e < 128 * 12; e += 256) {
        int r = e / 12, k = 20 + e % 12;
        *reinterpret_cast<unsigned short*>(sm + MA_H + (r * 40 + k) * 2) = 0;
        *reinterpret_cast<unsigned short*>(sm + MA_L + (r * 40 + k) * 2) = 0;
    }
    for (int e = tid; e < 128 * HID; e += 256) {
        int r = e / HID, jj = e % HID;
        const float* crow = cs + r * 10;
        float s = bm1[jj];
#pragma unroll
        for (int k = 0; k < DK; k++)
            s = fmaf(crow[k], Wm1[k * HID + jj], s);
        s = (s > 0.f) ? s : 0.01f * s;
        uint32_t bits = __float_as_uint(s);
        *reinterpret_cast<unsigned short*>(sm + MA_H + (r * 40 + jj) * 2) =
            (unsigned short)(bits >> 16);
        *reinterpret_cast<unsigned short*>(sm + MA_L + (r * 40 + jj) * 2) =
            bf16rn(s - __uint_as_float(bits & 0xFFFF0000u));
    }
    __syncthreads();

    const int arow = lane & 15;
    const int agrp = lane >> 4;
    uint32_t ah[2][4], al[2][4];
#pragma unroll
    for (int ks = 0; ks < 2; ks++) {
        uint32_t abase = (m0 + arow) * 80 + ks * 32 + agrp * 16;
        ldsm4(ah[ks], sb + MA_H + abase);
        ldsm4(al[ks], sb + MA_L + abase);
    }

    const int bn = lane >> 2;
    const int bj = (lane & 3) * 2;
    const int rC = lane >> 2;
    const int jC = lane & 3;

    for (int nc = 0; nc < 4; nc++) {
        __syncthreads();
        // B staging: pure uint4 copies of precomputed planes (stride 40 u16)
        for (int e = tid; e < 1280; e += 256) {
            int pl = e / 640, rem = e % 640;
            int row = rem / 5, q = rem % 5;
            const unsigned short* srcp = pl
                ? &g_W2l[nc * 128 + row][q * 8]
                : &g_W2h[nc * 128 + row][q * 8];
            *reinterpret_cast<uint4*>(
                sm + (pl ? MB_L : MB_H) + row * 80 + q * 16) =
                *reinterpret_cast<const uint4*>(srcp);
        }
        __syncthreads();

#pragma unroll 4
        for (int t = 0; t < 16; t++) {
            float C[4] = {0.f, 0.f, 0.f, 0.f};
#pragma unroll
            for (int ks = 0; ks < 2; ks++) {
                uint32_t bo = ((bn + t * 8) * 40 + ks * 16 + bj) * 2;
                uint32_t bh0 = *reinterpret_cast<const uint32_t*>(sm + MB_H + bo);
                uint32_t bh1 = *reinterpret_cast<const uint32_t*>(sm + MB_H + bo + 16);
                uint32_t bl0 = *reinterpret_cast<const uint32_t*>(sm + MB_L + bo);
                uint32_t bl1 = *reinterpret_cast<const uint32_t*>(sm + MB_L + bo + 16);
                mma_k16(C, ah[ks], bh0, bh1);
                mma_k16(C, ah[ks], bl0, bl1);
                mma_k16(C, al[ks], bh0, bh1);
            }
            int n0 = nc * 128 + t * 8;
            float b0 = bm2s[n0 + 2 * jC], b1 = bm2s[n0 + 2 * jC + 1];
            size_t ro = (size_t)(row0 + m0 + rC) * DOUT + n0 + 2 * jC;
            *reinterpret_cast<float2*>(out + ro) = make_float2(C[0] + b0, C[1] + b1);
            *reinterpret_cast<float2*>(out + ro + 8 * DOUT) = make_float2(C[2] + b0, C[3] + b1);
        }
    }
}

// =====================================================================
extern "C" void kernel_launch(void* const* d_in, const int* in_sizes, int n_in,
                              void* d_out, int out_size)
{
    const float* x   = (const float*)d_in[0];
    const float* Wq  = (const float*)d_in[1];
    const float* bq  = (const float*)d_in[2];
    const float* Wk  = (const float*)d_in[3];
    const float* bk  = (const float*)d_in[4];
    const float* Wv  = (const float*)d_in[5];
    const float* bv  = (const float*)d_in[6];
    const float* Wm1 = (const float*)d_in[7];
    const float* bm1 = (const float*)d_in[8];
    const float* Wm2 = (const float*)d_in[9];
    const float* bm2 = (const float*)d_in[10];

    prep<<<144, 256>>>(Wq, Wk, Wv, Wm2);
    proj_tc<<<ROWS / 128, 256>>>(x, bq, bk, bv);
    attn_tc<<<dim3(Nn / 128, 32, KZ), 256>>>();
    mlp_tc<<<ROWS / 128, 256>>>(Wm1, bm1, bm2, (float*)d_out);
}

// round 17
// speedup vs baseline: 1.3496x; 1.0225x over previous
#include <cuda_runtime.h>
#include <cuda_bf16.h>
#include <cstdint>

// ---------------- HMMA / misc helpers (family-portable: sm_80+) ----------------
__device__ __forceinline__ uint32_t smem_u32(const void* p) {
    uint32_t a;
    asm("{ .reg .u64 t; cvta.to.shared.u64 t, %1; cvt.u32.u64 %0, t; }" : "=r"(a) : "l"(p));
    return a;
}
__device__ __forceinline__ void ldsm4(uint32_t r[4], uint32_t addr) {
    asm volatile("ldmatrix.sync.aligned.m8n8.x4.shared.b16 {%0,%1,%2,%3}, [%4];"
        : "=r"(r[0]), "=r"(r[1]), "=r"(r[2]), "=r"(r[3]) : "r"(addr));
}
__device__ __forceinline__ void mma_k16(float c[4], const uint32_t a[4], uint32_t b0, uint32_t b1) {
    asm volatile("mma.sync.aligned.m16n8k16.row.col.f32.bf16.bf16.f32 "
        "{%0,%1,%2,%3}, {%4,%5,%6,%7}, {%8,%9}, {%0,%1,%2,%3};"
        : "+f"(c[0]), "+f"(c[1]), "+f"(c[2]), "+f"(c[3])
        : "r"(a[0]), "r"(a[1]), "r"(a[2]), "r"(a[3]), "r"(b0), "r"(b1));
}
__device__ __forceinline__ void mma_k8(float c[4], uint32_t a0, uint32_t a1, uint32_t b0) {
    asm volatile("mma.sync.aligned.m16n8k8.row.col.f32.bf16.bf16.f32 "
        "{%0,%1,%2,%3}, {%4,%5}, {%6}, {%0,%1,%2,%3};"
        : "+f"(c[0]), "+f"(c[1]), "+f"(c[2]), "+f"(c[3])
        : "r"(a0), "r"(a1), "r"(b0));
}
__device__ __forceinline__ uint32_t pbf2(float lo, float hi) {   // low half = lo
    uint32_t r; asm("cvt.rn.bf16x2.f32 %0, %1, %2;" : "=r"(r) : "f"(hi), "f"(lo)); return r;
}
__device__ __forceinline__ unsigned short bf16rn(float f) {
    unsigned short u; asm("cvt.rn.bf16.f32 %0, %1;" : "=h"(u) : "f"(f)); return u;
}
__device__ __forceinline__ float sin_ap(float x) {
    float r; asm("sin.approx.f32 %0, %1;" : "=f"(r) : "f"(x)); return r;
}
__device__ __forceinline__ float ex2_ap(float x) {
    float r; asm("ex2.approx.f32 %0, %1;" : "=f"(r) : "f"(x)); return r;
}
__device__ __forceinline__ void split2(float a, float b, uint32_t& h, uint32_t& l) {
    uint32_t ba = __float_as_uint(a), bb = __float_as_uint(b);
    h = __byte_perm(ba, bb, 0x7632);
    l = pbf2(a - __uint_as_float(ba & 0xFFFF0000u),
             b - __uint_as_float(bb & 0xFFFF0000u));
}

// ---------------- problem constants ----------------
#define Bn   16
#define Nn   2048
#define DIN  512
#define DK   10
#define NH   2
#define DH   5
#define HID  20
#define DOUT 512
#define ROWS (Bn * Nn)             // 32768
#define KZ   4

// ---------------- device scratch ----------------
__device__ uint32_t g_Qb[32][Nn][8];       // split-bf16: [0..3]=hi pairs, [4..7]=lo
__device__ uint32_t g_Kb[32][Nn][8];
__device__ unsigned short g_Vth[32][5][Nn];  // V transposed, hi plane
__device__ unsigned short g_Vtl[32][5][Nn];  // lo plane
__device__ float g_A[32][Nn][KZ][8];         // partials: a0..a4, den
// precomputed split-bf16 weights
__device__ __align__(16) unsigned short g_Wph[32][512];  // qkv W: [j][k] hi
__device__ __align__(16) unsigned short g_Wpl[32][512];  // lo
__device__ __align__(16) unsigned short g_W2h[512][40];  // Wm2: [n][k pad40] hi
__device__ __align__(16) unsigned short g_W2l[512][40];  // lo

// =====================================================================
// Kernel 0: one-time weight split-bf16 prep (W qkv + Wm2).
// =====================================================================
__global__ __launch_bounds__(256) void prep(
    const float* __restrict__ Wq, const float* __restrict__ Wk,
    const float* __restrict__ Wv, const float* __restrict__ Wm2)
{
    int idx = blockIdx.x * 256 + threadIdx.x;
    if (idx < 32 * 512) {
        int j = idx >> 9, k = idx & 511;
        float w = (j < 10) ? Wq[k * DK + j]
                : (j < 20) ? Wk[k * DK + (j - 10)]
                : (j < 30) ? Wv[k * DK + (j - 20)] : 0.f;
        uint32_t wb = __float_as_uint(w);
        g_Wph[j][k] = (unsigned short)(wb >> 16);
        g_Wpl[j][k] = bf16rn(w - __uint_as_float(wb & 0xFFFF0000u));
    } else if (idx < 32 * 512 + 512 * 40) {
        int e = idx - 32 * 512;
        int col = e / 40, k = e % 40;
        float w = (k < HID) ? Wm2[k * DOUT + col] : 0.f;
        uint32_t wb = __float_as_uint(w);
        g_W2h[col][k] = (unsigned short)(wb >> 16);
        g_W2l[col][k] = bf16rn(w - __uint_as_float(wb & 0xFFFF0000u));
    }
}

// =====================================================================
// Kernel 1: QKV projection on HMMA (R16 winner, unchanged).
// =====================================================================
#define XSTR 72
#define XH_OFF 0
#define XL_OFF (128 * XSTR * 2)
#define WH_OFF (2 * 128 * XSTR * 2)
#define WL_OFF (WH_OFF + 32 * XSTR * 2)
#define SM_TOT (WL_OFF + 32 * XSTR * 2)

__global__ __launch_bounds__(256) void proj_tc(
    const float* __restrict__ x,
    const float* __restrict__ bq, const float* __restrict__ bk,
    const float* __restrict__ bv)
{
    __shared__ __align__(16) char sm[SM_TOT];
    const uint32_t sb = smem_u32(sm);

    const int tid  = threadIdx.x;
    const int wid  = tid >> 5;
    const int lane = tid & 31;
    const int row0 = blockIdx.x * 128;
    const int m0   = wid * 16;

    float C[4][4];
#pragma unroll
    for (int t = 0; t < 4; t++)
#pragma unroll
        for (int i = 0; i < 4; i++) C[t][i] = 0.f;

    float4 xr[8];
    uint4  wr4[2];
#pragma unroll
    for (int it = 0; it < 8; it++) {
        int e = tid + it * 256;
        int r = e >> 4, c4 = e & 15;
        xr[it] = *reinterpret_cast<const float4*>(x + (size_t)(row0 + r) * DIN + c4 * 4);
    }
#pragma unroll
    for (int it = 0; it < 2; it++) {
        int e = tid + it * 256;
        int pl = e >> 8, rem = e & 255;
        int j = rem >> 3, q = rem & 7;
        const unsigned short* srcp = pl ? &g_Wpl[j][q * 8] : &g_Wph[j][q * 8];
        wr4[it] = *reinterpret_cast<const uint4*>(srcp);
    }

    const int arow = lane & 15;
    const int agrp = lane >> 4;
    const int bn = lane >> 2;
    const int bk0 = (lane & 3) * 2;

    for (int c = 0; c < 8; c++) {
        __syncthreads();
#pragma unroll
        for (int it = 0; it < 8; it++) {
            int e = tid + it * 256;
            int r = e >> 4, c4 = e & 15;
            float4 v = xr[it];
            uint32_t h01, l01, h23, l23;
            split2(v.x, v.y, h01, l01);
            split2(v.z, v.w, h23, l23);
            uint32_t off = (r * XSTR + c4 * 4) * 2;
            *reinterpret_cast<uint2*>(sm + XH_OFF + off) = make_uint2(h01, h23);
            *reinterpret_cast<uint2*>(sm + XL_OFF + off) = make_uint2(l01, l23);
        }
#pragma unroll
        for (int it = 0; it < 2; it++) {
            int e = tid + it * 256;
            int pl = e >> 8, rem = e & 255;
            int j = rem >> 3, q = rem & 7;
            *reinterpret_cast<uint4*>(
                sm + (pl ? WL_OFF : WH_OFF) + (j * XSTR + q * 8) * 2) = wr4[it];
        }
        __syncthreads();

        if (c < 7) {
            const int kc = (c + 1) * 64;
#pragma unroll
            for (int it = 0; it < 8; it++) {
                int e = tid + it * 256;
                int r = e >> 4, c4 = e & 15;
                xr[it] = *reinterpret_cast<const float4*>(
                    x + (size_t)(row0 + r) * DIN + kc + c4 * 4);
            }
#pragma unroll
            for (int it = 0; it < 2; it++) {
                int e = tid + it * 256;
                int pl = e >> 8, rem = e & 255;
                int j = rem >> 3, q = rem & 7;
                const unsigned short* srcp = pl ? &g_Wpl[j][kc + q * 8] : &g_Wph[j][kc + q * 8];
                wr4[it] = *reinterpret_cast<const uint4*>(srcp);
            }
        }

#pragma unroll
        for (int ks = 0; ks < 4; ks++) {
            uint32_t ah[4], al[4];
            uint32_t abase = (m0 + arow) * (XSTR * 2) + ks * 32 + agrp * 16;
            ldsm4(ah, sb + XH_OFF + abase);
            ldsm4(al, sb + XL_OFF + abase);
#pragma unroll
            for (int t = 0; t < 4; t++) {
                uint32_t boff = ((bn + t * 8) * XSTR + ks * 16 + bk0) * 2;
                uint32_t bh0 = *reinterpret_cast<const uint32_t*>(sm + WH_OFF + boff);
                uint32_t bh1 = *reinterpret_cast<const uint32_t*>(sm + WH_OFF + boff + 16);
                uint32_t bl0 = *reinterpret_cast<const uint32_t*>(sm + WL_OFF + boff);
                uint32_t bl1 = *reinterpret_cast<const uint32_t*>(sm + WL_OFF + boff + 16);
                mma_k16(C[t], ah, bh0, bh1);
                mma_k16(C[t], ah, bl0, bl1);
                mma_k16(C[t], al, bh0, bh1);
            }
        }
    }

    __syncthreads();
    float* co = reinterpret_cast<float*>(sm);
    {
        const int r_c = lane >> 2;
        const int j2  = (lane & 3) * 2;
#pragma unroll
        for (int t = 0; t < 4; t++) {
            float* p0 = co + (m0 + r_c) * 33 + t * 8 + j2;
            float* p1 = co + (m0 + r_c + 8) * 33 + t * 8 + j2;
            p0[0] = C[t][0]; p0[1] = C[t][1];
            p1[0] = C[t][2]; p1[1] = C[t][3];
        }
    }
    __syncthreads();

    if (tid < 128) {
        const float* src = co + tid * 33;
        float o[30];
#pragma unroll
        for (int j = 0; j < 30; j++) o[j] = src[j];

        const int grow = row0 + tid;
        const int b = grow >> 11, n = grow & (Nn - 1);
        const float rs = 0.4472135954999579f;   // 1/sqrt(5)

        float q[10], kk[10], vv[10];
#pragma unroll
        for (int j = 0; j < 10; j++) {
            q[j]  = (o[j]      + bq[j]) * rs;
            kk[j] = (o[j + 10] + bk[j]);
            vv[j] = (o[j + 20] + bv[j]);
        }
#pragma unroll
        for (int h = 0; h < 2; h++) {
            int bh = b * NH + h;
            uint32_t qh[4], ql[4], kh[4], kl[4];
            split2(q[h*5+0], q[h*5+1], qh[0], ql[0]);
            split2(q[h*5+2], q[h*5+3], qh[1], ql[1]);
            split2(q[h*5+4], 0.f,      qh[2], ql[2]);
            qh[3] = 0; ql[3] = 0;
            split2(kk[h*5+0], kk[h*5+1], kh[0], kl[0]);
            split2(kk[h*5+2], kk[h*5+3], kh[1], kl[1]);
            split2(kk[h*5+4], 0.f,       kh[2], kl[2]);
            kh[3] = 0; kl[3] = 0;
            *reinterpret_cast<uint4*>(&g_Qb[bh][n][0]) = make_uint4(qh[0], qh[1], qh[2], qh[3]);
            *reinterpret_cast<uint4*>(&g_Qb[bh][n][4]) = make_uint4(ql[0], ql[1], ql[2], ql[3]);
            *reinterpret_cast<uint4*>(&g_Kb[bh][n][0]) = make_uint4(kh[0], kh[1], kh[2], kh[3]);
            *reinterpret_cast<uint4*>(&g_Kb[bh][n][4]) = make_uint4(kl[0], kl[1], kl[2], kl[3]);
#pragma unroll
            for (int d = 0; d < 5; d++) {
                float v = vv[h*5+d];
                uint32_t vb = __float_as_uint(v);
                g_Vth[bh][d][n] = (unsigned short)(vb >> 16);
                g_Vtl[bh][d][n] = bf16rn(v - __uint_as_float(vb & 0xFFFF0000u));
            }
        }
    }
}

// =====================================================================
// Kernel 2: HMMA attention (R16 config) with PV accumulator chain split
// into 3 independent accumulators (by product type).
// =====================================================================
#define AQH 0
#define AQL 2048
#define AKH 4096
#define AKL 6144
#define AVH 8192
#define AVL (AVH + 8 * 136 * 2)       // 10368
#define AT_SM (AVL + 8 * 136 * 2)     // 12544

__global__ __launch_bounds__(256) void attn_tc()
{
    __shared__ __align__(16) char sm[AT_SM];

    const int tid  = threadIdx.x;
    const int wid  = tid >> 5;
    const int lane = tid & 31;
    const int qt   = (Nn / 128 - 1) - blockIdx.x;    // heavy tiles first
    const int bh   = blockIdx.y;
    const int kz   = blockIdx.z;
    const int m0   = wid * 16;
    const int r    = lane >> 2;
    const int j    = lane & 3;

    const int nt = qt + 1;
    const int t0 = (nt * kz) / KZ, t1 = (nt * (kz + 1)) / KZ;

    float Cp1[4] = {0.f,0.f,0.f,0.f};
    float Cp2[4] = {0.f,0.f,0.f,0.f};
    float Cp3[4] = {0.f,0.f,0.f,0.f};
    const float LOG2E = 1.4426950408889634f;

    if (t0 < t1) {
        for (int e = tid; e < 3 * 136; e += 256) {
            int d = 5 + e / 136, kk2 = e % 136;
            *reinterpret_cast<unsigned short*>(sm + AVH + (d * 136 + kk2) * 2) =
                (d == 5) ? (unsigned short)0x3F80 : (unsigned short)0;
            *reinterpret_cast<unsigned short*>(sm + AVL + (d * 136 + kk2) * 2) = 0;
        }
        if (tid < 128) {
            uint4 h = *reinterpret_cast<const uint4*>(&g_Qb[bh][qt * 128 + tid][0]);
            uint4 l = *reinterpret_cast<const uint4*>(&g_Qb[bh][qt * 128 + tid][4]);
            *reinterpret_cast<uint4*>(sm + AQH + tid * 16) = h;
            *reinterpret_cast<uint4*>(sm + AQL + tid * 16) = l;
        }
        __syncthreads();

        uint32_t Aq[4];   // [Qh(k0-7) | Ql(k8-15)] merged A-frag
        uint32_t qh0, qh1;
        {
            uint32_t w0 = (m0 + r) * 16 + j * 4;
            uint32_t w1 = (m0 + r + 8) * 16 + j * 4;
            qh0 = *reinterpret_cast<const uint32_t*>(sm + AQH + w0);
            qh1 = *reinterpret_cast<const uint32_t*>(sm + AQH + w1);
            Aq[0] = qh0;
            Aq[1] = qh1;
            Aq[2] = *reinterpret_cast<const uint32_t*>(sm + AQL + w0);
            Aq[3] = *reinterpret_cast<const uint32_t*>(sm + AQL + w1);
        }

        uint32_t vr[5];
        uint4 kh4, kl4;
        const int key = tid & 127;

        {
            const int key0 = t0 * 128;
            if (tid < 128) {
#pragma unroll
                for (int it = 0; it < 5; it++) {
                    int e = tid + it * 128;
                    int pl = e / 320, rem = e % 320;
                    int d = rem >> 6, kp = rem & 63;
                    vr[it] = pl
                        ? *reinterpret_cast<const uint32_t*>(&g_Vtl[bh][d][key0 + 2 * kp])
                        : *reinterpret_cast<const uint32_t*>(&g_Vth[bh][d][key0 + 2 * kp]);
                }
            } else {
                kh4 = *reinterpret_cast<const uint4*>(&g_Kb[bh][key0 + key][0]);
                kl4 = *reinterpret_cast<const uint4*>(&g_Kb[bh][key0 + key][4]);
            }
        }

        for (int ck = t0; ck < t1; ck++) {
            __syncthreads();
            if (tid < 128) {
#pragma unroll
                for (int it = 0; it < 5; it++) {
                    int e = tid + it * 128;
                    int pl = e / 320, rem = e % 320;
                    int d = rem >> 6, kp = rem & 63;
                    *reinterpret_cast<uint32_t*>(
                        sm + (pl ? AVL : AVH) + (d * 136 + 2 * kp) * 2) = vr[it];
                }
            } else {
                *reinterpret_cast<uint4*>(sm + AKH + key * 16) = kh4;
                *reinterpret_cast<uint4*>(sm + AKL + key * 16) = kl4;
            }
            __syncthreads();

            if (ck + 1 < t1) {
                const int key0 = (ck + 1) * 128;
                if (tid < 128) {
#pragma unroll
                    for (int it = 0; it < 5; it++) {
                        int e = tid + it * 128;
                        int pl = e / 320, rem = e % 320;
                        int d = rem >> 6, kp = rem & 63;
                        vr[it] = pl
                            ? *reinterpret_cast<const uint32_t*>(&g_Vtl[bh][d][key0 + 2 * kp])
                            : *reinterpret_cast<const uint32_t*>(&g_Vth[bh][d][key0 + 2 * kp]);
                    }
                } else {
                    kh4 = *reinterpret_cast<const uint4*>(&g_Kb[bh][key0 + key][0]);
                    kl4 = *reinterpret_cast<const uint4*>(&g_Kb[bh][key0 + key][4]);
                }
            }

            const bool diag = (ck == qt);

#pragma unroll 2
            for (int ks = 0; ks < 8; ks++) {
                const int kbase = ks * 16;
                if (diag && kbase > m0 + 15) break;
                const bool needMask = diag && (kbase + 15 > m0);

                float c0[4] = {0.f,0.f,0.f,0.f}, c1[4] = {0.f,0.f,0.f,0.f};
                {
                    uint32_t o0 = (kbase + r) * 16 + j * 4;
                    uint32_t o1 = (kbase + 8 + r) * 16 + j * 4;
                    uint32_t b0h = *reinterpret_cast<const uint32_t*>(sm + AKH + o0);
                    uint32_t b0l = *reinterpret_cast<const uint32_t*>(sm + AKL + o0);
                    uint32_t b1h = *reinterpret_cast<const uint32_t*>(sm + AKH + o1);
                    uint32_t b1l = *reinterpret_cast<const uint32_t*>(sm + AKL + o1);
                    mma_k16(c0, Aq, b0h, b0h);     // Qh*Kh + Ql*Kh
                    mma_k8(c0, qh0, qh1, b0l);     // Qh*Kl
                    mma_k16(c1, Aq, b1h, b1h);
                    mma_k8(c1, qh0, qh1, b1l);
                }

                float p[8];
#pragma unroll
                for (int i = 0; i < 4; i++) p[i]     = ex2_ap(sin_ap(c0[i]) * LOG2E);
#pragma unroll
                for (int i = 0; i < 4; i++) p[4 + i] = ex2_ap(sin_ap(c1[i]) * LOG2E);

                if (needMask) {
                    int q_lo = m0 + r, q_hi = q_lo + 8;
                    int k00 = kbase + 2 * j, k01 = k00 + 1;
                    int k10 = k00 + 8,       k11 = k01 + 8;
                    p[0] = (k00 <= q_lo) ? p[0] : 0.f;
                    p[1] = (k01 <= q_lo) ? p[1] : 0.f;
                    p[2] = (k00 <= q_hi) ? p[2] : 0.f;
                    p[3] = (k01 <= q_hi) ? p[3] : 0.f;
                    p[4] = (k10 <= q_lo) ? p[4] : 0.f;
                    p[5] = (k11 <= q_lo) ? p[5] : 0.f;
                    p[6] = (k10 <= q_hi) ? p[6] : 0.f;
                    p[7] = (k11 <= q_hi) ? p[7] : 0.f;
                }

                uint32_t ah[4], al[4];
#pragma unroll
                for (int i = 0; i < 4; i++) {
                    uint32_t h = pbf2(p[2*i], p[2*i+1]);
                    ah[i] = h;
                    float r0 = __uint_as_float(h << 16);
                    float r1 = __uint_as_float(h & 0xFFFF0000u);
                    al[i] = pbf2(p[2*i] - r0, p[2*i+1] - r1);
                }

                uint32_t vo = (r * 136 + kbase + 2 * j) * 2;
                uint32_t bvh0 = *reinterpret_cast<const uint32_t*>(sm + AVH + vo);
                uint32_t bvh1 = *reinterpret_cast<const uint32_t*>(sm + AVH + vo + 16);
                uint32_t bvl0 = *reinterpret_cast<const uint32_t*>(sm + AVL + vo);
                uint32_t bvl1 = *reinterpret_cast<const uint32_t*>(sm + AVL + vo + 16);

                mma_k16(Cp1, ah, bvh0, bvh1);     // 3 independent chains
                mma_k16(Cp2, ah, bvl0, bvl1);
                mma_k16(Cp3, al, bvh0, bvh1);
            }
        }
    }

    if (j < 3) {
        float s0 = Cp1[0] + Cp2[0] + Cp3[0];
        float s1 = Cp1[1] + Cp2[1] + Cp3[1];
        float s2 = Cp1[2] + Cp2[2] + Cp3[2];
        float s3 = Cp1[3] + Cp2[3] + Cp3[3];
        int q1 = qt * 128 + m0 + r;
        *reinterpret_cast<float2*>(&g_A[bh][q1][kz][2 * j]) = make_float2(s0, s1);
        int q2 = q1 + 8;
        *reinterpret_cast<float2*>(&g_A[bh][q2][kz][2 * j]) = make_float2(s2, s3);
    }
}

// =====================================================================
// Kernel 3: combine partials + MLP head on HMMA.
// B staging register double-buffered; 3 accumulators per tile (chain 2).
// =====================================================================
#define MA_H 0
#define MA_L 10240
#define MB_H 20480
#define MB_L 30720
#define MCS  40960
#define MBM2 46080
#define MLP_SM (MBM2 + 512 * 4)    // 48128

__global__ __launch_bounds__(256) void mlp_tc(
    const float* __restrict__ Wm1, const float* __restrict__ bm1,
    const float* __restrict__ bm2,
    float* __restrict__ out)
{
    __shared__ __align__(16) char sm[MLP_SM];
    const uint32_t sb = smem_u32(sm);

    const int tid  = threadIdx.x;
    const int wid  = tid >> 5;
    const int lane = tid & 31;
    const int row0 = blockIdx.x * 128;
    const int m0   = wid * 16;

    float* cs   = reinterpret_cast<float*>(sm + MCS);
    float* bm2s = reinterpret_cast<float*>(sm + MBM2);

    // B copy mapping (fixed per thread)
    const int be   = tid;                 // base element; its: +256 steps
    // precompute per-it mapping
    int bpl[5], brow[5], bq_[5];
#pragma unroll
    for (int it = 0; it < 5; it++) {
        int e = be + it * 256;
        bpl[it]  = e / 640;
        int rem  = e % 640;
        brow[it] = rem / 5;
        bq_[it]  = rem % 5;
    }

    // prefetch B chunk 0
    uint4 br4[5];
#pragma unroll
    for (int it = 0; it < 5; it++) {
        const unsigned short* srcp = bpl[it]
            ? &g_W2l[brow[it]][bq_[it] * 8]
            : &g_W2h[brow[it]][bq_[it] * 8];
        br4[it] = *reinterpret_cast<const uint4*>(srcp);
    }

    for (int e = tid; e < 128 * 10; e += 256) {
        int r = e / 10, k = e % 10;
        int h = k / DH, d = k % DH;
        int grow = row0 + r;
        int b = grow >> 11, n = grow & (Nn - 1);
        const float* A = g_A[b * NH + h][n][0];
        float den = 0.f, num = 0.f;
#pragma unroll
        for (int s = 0; s < KZ; s++) {
            num += A[8 * s + d];
            den += A[8 * s + 5];
        }
        cs[e] = num * __fdividef(1.f, den);
    }
    for (int e = tid; e < 512; e += 256) bm2s[e] = bm2[e];
    __syncthreads();

    for (int e = tid; e < 128 * 12; e += 256) {
        int r = e / 12, k = 20 + e % 12;
        *reinterpret_cast<unsigned short*>(sm + MA_H + (r * 40 + k) * 2) = 0;
        *reinterpret_cast<unsigned short*>(sm + MA_L + (r * 40 + k) * 2) = 0;
    }
    for (int e = tid; e < 128 * HID; e += 256) {
        int r = e / HID, jj = e % HID;
        const float* crow = cs + r * 10;
        float s = bm1[jj];
#pragma unroll
        for (int k = 0; k < DK; k++)
            s = fmaf(crow[k], Wm1[k * HID + jj], s);
        s = (s > 0.f) ? s : 0.01f * s;
        uint32_t bits = __float_as_uint(s);
        *reinterpret_cast<unsigned short*>(sm + MA_H + (r * 40 + jj) * 2) =
            (unsigned short)(bits >> 16);
        *reinterpret_cast<unsigned short*>(sm + MA_L + (r * 40 + jj) * 2) =
            bf16rn(s - __uint_as_float(bits & 0xFFFF0000u));
    }
    __syncthreads();

    const int arow = lane & 15;
    const int agrp = lane >> 4;
    uint32_t ah[2][4], al[2][4];
#pragma unroll
    for (int ks = 0; ks < 2; ks++) {
        uint32_t abase = (m0 + arow) * 80 + ks * 32 + agrp * 16;
        ldsm4(ah[ks], sb + MA_H + abase);
        ldsm4(al[ks], sb + MA_L + abase);
    }

    const int bn = lane >> 2;
    const int bj = (lane & 3) * 2;
    const int rC = lane >> 2;
    const int jC = lane & 3;

    for (int nc = 0; nc < 4; nc++) {
        __syncthreads();
        // store prefetched B chunk
#pragma unroll
        for (int it = 0; it < 5; it++) {
            *reinterpret_cast<uint4*>(
                sm + (bpl[it] ? MB_L : MB_H) + brow[it] * 80 + bq_[it] * 16) = br4[it];
        }
        __syncthreads();

        // prefetch next B chunk (overlaps compute)
        if (nc < 3) {
#pragma unroll
            for (int it = 0; it < 5; it++) {
                const unsigned short* srcp = bpl[it]
                    ? &g_W2l[(nc + 1) * 128 + brow[it]][bq_[it] * 8]
                    : &g_W2h[(nc + 1) * 128 + brow[it]][bq_[it] * 8];
                br4[it] = *reinterpret_cast<const uint4*>(srcp);
            }
        }

#pragma unroll 4
        for (int t = 0; t < 16; t++) {
            float C1[4] = {0.f,0.f,0.f,0.f};
            float C2[4] = {0.f,0.f,0.f,0.f};
            float C3[4] = {0.f,0.f,0.f,0.f};
#pragma unroll
            for (int ks = 0; ks < 2; ks++) {
                uint32_t bo = ((bn + t * 8) * 40 + ks * 16 + bj) * 2;
                uint32_t bh0 = *reinterpret_cast<const uint32_t*>(sm + MB_H + bo);
                uint32_t bh1 = *reinterpret_cast<const uint32_t*>(sm + MB_H + bo + 16);
                uint32_t bl0 = *reinterpret_cast<const uint32_t*>(sm + MB_L + bo);
                uint32_t bl1 = *reinterpret_cast<const uint32_t*>(sm + MB_L + bo + 16);
                mma_k16(C1, ah[ks], bh0, bh1);
                mma_k16(C2, ah[ks], bl0, bl1);
                mma_k16(C3, al[ks], bh0, bh1);
            }
            int n0 = nc * 128 + t * 8;
            float b0 = bm2s[n0 + 2 * jC], b1 = bm2s[n0 + 2 * jC + 1];
            float o0 = C1[0] + C2[0] + C3[0] + b0;
            float o1 = C1[1] + C2[1] + C3[1] + b1;
            float o2 = C1[2] + C2[2] + C3[2] + b0;
            float o3 = C1[3] + C2[3] + C3[3] + b1;
            size_t ro = (size_t)(row0 + m0 + rC) * DOUT + n0 + 2 * jC;
            *reinterpret_cast<float2*>(out + ro) = make_float2(o0, o1);
            *reinterpret_cast<float2*>(out + ro + 8 * DOUT) = make_float2(o2, o3);
        }
    }
}

// =====================================================================
extern "C" void kernel_launch(void* const* d_in, const int* in_sizes, int n_in,
                              void* d_out, int out_size)
{
    const float* x   = (const float*)d_in[0];
    const float* Wq  = (const float*)d_in[1];
    const float* bq  = (const float*)d_in[2];
    const float* Wk  = (const float*)d_in[3];
    const float* bk  = (const float*)d_in[4];
    const float* Wv  = (const float*)d_in[5];
    const float* bv  = (const float*)d_in[6];
    const float* Wm1 = (const float*)d_in[7];
    const float* bm1 = (const float*)d_in[8];
    const float* Wm2 = (const float*)d_in[9];
    const float* bm2 = (const float*)d_in[10];

    prep<<<144, 256>>>(Wq, Wk, Wv, Wm2);
    proj_tc<<<ROWS / 128, 256>>>(x, bq, bk, bv);
    attn_tc<<<dim3(Nn / 128, 32, KZ), 256>>>();
    mlp_tc<<<ROWS / 128, 256>>>(Wm1, bm1, bm2, (float*)d_out);
}